// round 12
// baseline (speedup 1.0000x reference)
#include <cuda_runtime.h>
#include <cuda_bf16.h>
#include <cuda_fp16.h>
#include <math.h>
#include <stdint.h>

// Problem constants
#define BB   2
#define SS   2048
#define DIM  4096
#define NH   32
#define NKV  8
#define HD   128
#define NT   (BB*SS)          // 4096 tokens
#define QDIM (NH*HD)          // 4096
#define KDIM (NKV*HD)         // 1024

// ---------------- scratch (device globals; no allocation allowed) ----------
__device__ float g_Q[NT * QDIM];
__device__ float g_K[NT * KDIM];
__device__ float g_V[NT * KDIM];
// fp16 projection operands (2-term split: activations hi+lo, weights single)
__device__ __half g_xh[NT * DIM];
__device__ __half g_xl[NT * DIM];
__device__ __half g_Wqh[QDIM * DIM];     // transposed [N][K]
__device__ __half g_Wkh[KDIM * DIM];
__device__ __half g_Wvh[KDIM * DIM];
__device__ __half g_Woh[DIM * QDIM];
__device__ __half g_Ah[NT * QDIM];       // attention out hi (fp16)
__device__ __half g_Al[NT * QDIM];       // attention out lo (fp16)
// fp16 attention operands
__device__ __half g_Qah[NT * QDIM];      // Q hi (exact split)
__device__ __half g_Qal[NT * QDIM];      // Q lo
__device__ __half g_Kah[NT * KDIM];      // K single fp16
__device__ __half g_Vt[BB * NKV * HD * SS];  // V transposed [b][g][d][s], single fp16

// ======================= PTX helpers =======================
__device__ __forceinline__ uint32_t smem_u32(const void* p) {
    uint32_t a;
    asm("{ .reg .u64 t; cvta.to.shared.u64 t, %1; cvt.u32.u64 %0, t; }" : "=r"(a) : "l"(p));
    return a;
}
__device__ __forceinline__ void cp_async16(uint32_t dst, const void* src) {
    asm volatile("cp.async.cg.shared.global [%0], [%1], 16;" :: "r"(dst), "l"(src));
}
#define CP_COMMIT() asm volatile("cp.async.commit_group;" ::: "memory")
#define CP_WAIT0()  asm volatile("cp.async.wait_group 0;" ::: "memory")
#define CP_WAIT1()  asm volatile("cp.async.wait_group 1;" ::: "memory")

__device__ __forceinline__ uint32_t sw128(uint32_t b) { return b ^ ((b >> 3) & 0x70); }

__device__ __forceinline__ float exp2a(float x) {
    float r;
    asm("ex2.approx.f32 %0, %1;" : "=f"(r) : "f"(x));
    return r;
}

#define LDSM4(r, addr) \
    asm volatile("ldmatrix.sync.aligned.m8n8.x4.shared.b16 {%0,%1,%2,%3}, [%4];" \
        : "=r"((r)[0]), "=r"((r)[1]), "=r"((r)[2]), "=r"((r)[3]) : "r"(addr))

#define MMAH16816(c, a, b0, b1) \
    asm volatile("mma.sync.aligned.m16n8k16.row.col.f32.f16.f16.f32 " \
        "{%0,%1,%2,%3}, {%4,%5,%6,%7}, {%8,%9}, {%0,%1,%2,%3};" \
        : "+f"((c)[0]), "+f"((c)[1]), "+f"((c)[2]), "+f"((c)[3]) \
        : "r"((a)[0]), "r"((a)[1]), "r"((a)[2]), "r"((a)[3]), "r"(b0), "r"(b1))

// =============== fp16 2-term HMMA GEMM, 128x256 tile, 3-stage pipeline ======
// C[M,N] = (Ah+Al)[M,K] * Bh^T, B [N,K] row-major fp16.
// smem/stage: Ah 16K | Al 16K | Bh 32K = 64KB; 3 stages = 192KB.
#define GSMEM_BYTES (3 * 65536)

__device__ __forceinline__ void load_stage_part(
    uint32_t buf, const __half* Ah, const __half* Al, const __half* Bh,
    int row0, int col0, int K, int kchunk, int tid, int part)
{
    #pragma unroll
    for (int j = 0; j < 4; j++) {
        const int c = tid + part * 1024 + j * 256;
        if (c < 1024) {
            const int r = c >> 3, sg = c & 7;
            const uint32_t dst = buf + sw128(r * 128 + sg * 16);
            cp_async16(dst, Ah + (size_t)(row0 + r) * K + kchunk * 64 + sg * 8);
        } else if (c < 2048) {
            const int idx = c - 1024;
            const int r = idx >> 3, sg = idx & 7;
            const uint32_t dst = buf + 16384 + sw128(r * 128 + sg * 16);
            cp_async16(dst, Al + (size_t)(row0 + r) * K + kchunk * 64 + sg * 8);
        } else {
            const int idx = c - 2048;
            const int r = idx >> 3, sg = idx & 7;      // r 0..255
            const uint32_t dst = buf + 32768 + sw128(r * 128 + sg * 16);
            cp_async16(dst, Bh + (size_t)(col0 + r) * K + kchunk * 64 + sg * 8);
        }
    }
}

__global__ __launch_bounds__(256, 1) void gemm_fp16x2(
    const __half* __restrict__ Ah, const __half* __restrict__ Al,
    const __half* __restrict__ Bh,
    float* __restrict__ C, int M, int N, int K)
{
    extern __shared__ char smc[];
    const uint32_t sb = smem_u32(smc);
    const int tid = threadIdx.x;
    const int wid = tid >> 5;
    const int lane = tid & 31;
    const int row0 = blockIdx.y * 128;
    const int col0 = blockIdx.x * 256;
    const int nz = gridDim.z;
    const int K2 = K / nz;
    const int kb = blockIdx.z * (K2 / 64);

    const int wm0 = (wid >> 2) * 64;
    const int wn0 = (wid & 3) * 64;

    float acc[4][8][4];
    #pragma unroll
    for (int i = 0; i < 4; i++)
        #pragma unroll
        for (int j = 0; j < 8; j++)
            #pragma unroll
            for (int r = 0; r < 4; r++) acc[i][j][r] = 0.f;

    const int KT = K2 / 64;
    // prologue: stages 0 and 1
    #pragma unroll
    for (int p = 0; p < 4; p++)
        load_stage_part(sb, Ah, Al, Bh, row0, col0, K, kb, tid, p);
    CP_COMMIT();
    if (KT > 1) {
        #pragma unroll
        for (int p = 0; p < 4; p++)
            load_stage_part(sb + 65536, Ah, Al, Bh, row0, col0, K, kb + 1, tid, p);
        CP_COMMIT();
    }

    // buffer index trackers (avoid %3)
    int bi = 0;   // buffer of stage it
    int ni = (KT > 1) ? 2 : 1;  // buffer for stage it+2

    for (int it = 0; it < KT; it++) {
        if (it + 1 < KT) { CP_WAIT1(); } else { CP_WAIT0(); }
        __syncthreads();
        const uint32_t buf = sb + bi * 65536;
        const bool more2 = (it + 2 < KT);
        const uint32_t nbuf = sb + ni * 65536;

        const uint32_t aHb = buf;
        const uint32_t aLb = buf + 16384;
        const uint32_t bHb = buf + 32768;

        #pragma unroll
        for (int k16 = 0; k16 < 4; k16++) {
            if (more2) {
                load_stage_part(nbuf, Ah, Al, Bh, row0, col0, K, kb + it + 2, tid, k16);
                if (k16 == 3) CP_COMMIT();
            }
            const int colb = k16 * 32 + (lane >> 4) * 16;
            uint32_t ah[4][4], al[4][4];
            #pragma unroll
            for (int mi = 0; mi < 4; mi++) {
                const uint32_t off = sw128((wm0 + mi * 16 + (lane & 15)) * 128 + colb);
                LDSM4(ah[mi], aHb + off);
                LDSM4(al[mi], aLb + off);
            }
            #pragma unroll
            for (int hb = 0; hb < 2; hb++) {
                uint32_t bh[2][4];
                #pragma unroll
                for (int np = 0; np < 2; np++) {
                    const uint32_t off =
                        sw128((wn0 + hb * 32 + np * 16 + (lane & 15)) * 128 + colb);
                    LDSM4(bh[np], bHb + off);
                }
                #pragma unroll
                for (int mi = 0; mi < 4; mi++)
                    #pragma unroll
                    for (int nj = 0; nj < 4; nj++) {
                        const int np = nj >> 1, h = nj & 1;
                        MMAH16816(acc[mi][hb * 4 + nj], ah[mi], bh[np][h], bh[np][2 + h]);
                    }
                #pragma unroll
                for (int mi = 0; mi < 4; mi++)
                    #pragma unroll
                    for (int nj = 0; nj < 4; nj++) {
                        const int np = nj >> 1, h = nj & 1;
                        MMAH16816(acc[mi][hb * 4 + nj], al[mi], bh[np][h], bh[np][2 + h]);
                    }
            }
        }
        bi = (bi == 2) ? 0 : bi + 1;
        ni = (ni == 2) ? 0 : ni + 1;
    }

    if (nz > 1) {
        #pragma unroll
        for (int mi = 0; mi < 4; mi++) {
            #pragma unroll
            for (int nj = 0; nj < 8; nj++) {
                const int row = row0 + wm0 + mi * 16 + (lane >> 2);
                const int col = col0 + wn0 + nj * 8 + (lane & 3) * 2;
                float* p0 = C + (size_t)row * N + col;
                float* p1 = C + (size_t)(row + 8) * N + col;
                atomicAdd(p0,     acc[mi][nj][0]);
                atomicAdd(p0 + 1, acc[mi][nj][1]);
                atomicAdd(p1,     acc[mi][nj][2]);
                atomicAdd(p1 + 1, acc[mi][nj][3]);
            }
        }
    } else {
        #pragma unroll
        for (int mi = 0; mi < 4; mi++) {
            #pragma unroll
            for (int nj = 0; nj < 8; nj++) {
                const int row = row0 + wm0 + mi * 16 + (lane >> 2);
                const int col = col0 + wn0 + nj * 8 + (lane & 3) * 2;
                *(float2*)(C + (size_t)row * N + col)       = make_float2(acc[mi][nj][0], acc[mi][nj][1]);
                *(float2*)(C + (size_t)(row + 8) * N + col) = make_float2(acc[mi][nj][2], acc[mi][nj][3]);
            }
        }
    }
}

// =============== fp32 -> fp16 hi/lo split (row-major) ===========
__global__ void split_rows_h(const float* __restrict__ X,
                             __half* __restrict__ Xh,
                             __half* __restrict__ Xl, int total4)
{
    int i = blockIdx.x * blockDim.x + threadIdx.x;
    if (i >= total4) return;
    float4 v = *(const float4*)(X + (size_t)i * 4);
    __half h[4], l[4];
    float vv[4] = {v.x, v.y, v.z, v.w};
    #pragma unroll
    for (int j = 0; j < 4; j++) {
        h[j] = __float2half_rn(vv[j]);
        l[j] = __float2half_rn(vv[j] - __half2float(h[j]));
    }
    *(uint2*)(Xh + (size_t)i * 4) = *(uint2*)h;
    *(uint2*)(Xl + (size_t)i * 4) = *(uint2*)l;
}

// =============== transpose + fp16 quantize: W[K,N] fp32 -> T [N,K] fp16 =====
__global__ __launch_bounds__(256) void transpose_h(
    const float* __restrict__ W, __half* __restrict__ Th, int Kd, int Nd)
{
    __shared__ float t[64][65];
    const int n0 = blockIdx.x * 64, k0 = blockIdx.y * 64;
    const int tid = threadIdx.x;
    #pragma unroll
    for (int i = 0; i < 4; i++) {
        int it = tid + i * 256;
        int r = it >> 4;
        int c4 = (it & 15) * 4;
        float4 v = *(const float4*)(W + (size_t)(k0 + r) * Nd + n0 + c4);
        t[r][c4] = v.x; t[r][c4 + 1] = v.y; t[r][c4 + 2] = v.z; t[r][c4 + 3] = v.w;
    }
    __syncthreads();
    #pragma unroll
    for (int i = 0; i < 4; i++) {
        int it = tid + i * 256;
        int n = it >> 4;
        int kc = (it & 15) * 4;
        __half h[4];
        #pragma unroll
        for (int j = 0; j < 4; j++) h[j] = __float2half_rn(t[kc + j][n]);
        *(uint2*)(Th + (size_t)(n0 + n) * Kd + k0 + kc) = *(uint2*)h;
    }
}

// =============== RoPE + fp16 hi/lo split (Q) =================================
__global__ void rope_q_h(const float* __restrict__ X,
                         const float* __restrict__ cosT,
                         const float* __restrict__ sinT,
                         __half* __restrict__ Xh,
                         __half* __restrict__ Xl)
{
    int idx = blockIdx.x * blockDim.x + threadIdx.x;
    int total = NT * NH * 32;
    if (idx >= total) return;
    int j = idx & 31;
    int hh = (idx >> 5) % NH;
    int t = idx / (32 * NH);
    int s = t & (SS - 1);
    int d = 2 * j;

    const float* p = X + (size_t)t * QDIM + hh * HD;
    float x0 = p[d], x1 = p[d + 1], y0 = p[d + 64], y1 = p[d + 65];
    const float* cp = cosT + s * HD;
    const float* sp = sinT + s * HD;
    float r0 = x0 * cp[d]      - y0 * sp[d];
    float r1 = x1 * cp[d + 1]  - y1 * sp[d + 1];
    float r2 = y0 * cp[d + 64] + x0 * sp[d + 64];
    float r3 = y1 * cp[d + 65] + x1 * sp[d + 65];

    size_t o0 = (size_t)t * QDIM + hh * HD + d;
    __half h0 = __float2half_rn(r0), h1 = __float2half_rn(r1);
    __half h2 = __float2half_rn(r2), h3 = __float2half_rn(r3);
    __half q0 = __float2half_rn(r0 - __half2float(h0));
    __half q1 = __float2half_rn(r1 - __half2float(h1));
    __half q2 = __float2half_rn(r2 - __half2float(h2));
    __half q3 = __float2half_rn(r3 - __half2float(h3));
    __half hp[2] = {h0, h1};  *(uint32_t*)(Xh + o0) = *(uint32_t*)hp;
    __half lp[2] = {q0, q1};  *(uint32_t*)(Xl + o0) = *(uint32_t*)lp;
    __half hp2[2] = {h2, h3}; *(uint32_t*)(Xh + o0 + 64) = *(uint32_t*)hp2;
    __half lp2[2] = {q2, q3}; *(uint32_t*)(Xl + o0 + 64) = *(uint32_t*)lp2;
}

// =============== RoPE single fp16 (K) ========================================
__global__ void rope_k_h(const float* __restrict__ X,
                         const float* __restrict__ cosT,
                         const float* __restrict__ sinT,
                         __half* __restrict__ Xh)
{
    int idx = blockIdx.x * blockDim.x + threadIdx.x;
    int total = NT * NKV * 32;
    if (idx >= total) return;
    int j = idx & 31;
    int hh = (idx >> 5) % NKV;
    int t = idx / (32 * NKV);
    int s = t & (SS - 1);
    int d = 2 * j;

    const float* p = X + (size_t)t * KDIM + hh * HD;
    float x0 = p[d], x1 = p[d + 1], y0 = p[d + 64], y1 = p[d + 65];
    const float* cp = cosT + s * HD;
    const float* sp = sinT + s * HD;
    float r0 = x0 * cp[d]      - y0 * sp[d];
    float r1 = x1 * cp[d + 1]  - y1 * sp[d + 1];
    float r2 = y0 * cp[d + 64] + x0 * sp[d + 64];
    float r3 = y1 * cp[d + 65] + x1 * sp[d + 65];

    size_t o0 = (size_t)t * KDIM + hh * HD + d;
    __half hp[2]  = {__float2half_rn(r0), __float2half_rn(r1)};
    __half hp2[2] = {__float2half_rn(r2), __float2half_rn(r3)};
    *(uint32_t*)(Xh + o0)      = *(uint32_t*)hp;
    *(uint32_t*)(Xh + o0 + 64) = *(uint32_t*)hp2;
}

// =============== V: fp32 [NT][KDIM] -> transposed fp16 [b][g][d][s] ==========
__global__ __launch_bounds__(256) void v_t_h(const float* __restrict__ V,
                                             __half* __restrict__ Vt)
{
    __shared__ float t[64][65];
    const int c0 = blockIdx.x * 64;
    const int r0 = blockIdx.y * 64;
    const int tid = threadIdx.x;
    #pragma unroll
    for (int i = 0; i < 4; i++) {
        int it = tid + i * 256;
        int r = it >> 4;
        int c4 = (it & 15) * 4;
        float4 v = *(const float4*)(V + (size_t)(r0 + r) * KDIM + c0 + c4);
        t[r][c4] = v.x; t[r][c4 + 1] = v.y; t[r][c4 + 2] = v.z; t[r][c4 + 3] = v.w;
    }
    __syncthreads();
    const int b = r0 >> 11;
    const int sbase = r0 & (SS - 1);
    #pragma unroll
    for (int i = 0; i < 4; i++) {
        int it = tid + i * 256;
        int n = it >> 4;
        int kc = (it & 15) * 4;
        int col = c0 + n;
        int g = col >> 7;
        int d = col & 127;
        __half h[4];
        #pragma unroll
        for (int j = 0; j < 4; j++) h[j] = __float2half_rn(t[kc + j][n]);
        size_t o = ((size_t)((b * NKV + g) * HD) + d) * SS + sbase + kc;
        *(uint2*)(Vt + o) = *(uint2*)h;
    }
}

// ---------------- fp16 2-term flash attention (causal, GQA, 3-stage KV) -----
// smem: Qh 32KB | Ql 32KB | 3 stages x (K 16KB + Vt 16KB) = 160KB
#define ASMEM_BYTES (65536 + 3 * 32768)

__device__ __forceinline__ void attn_load_kv(
    uint32_t st, const __half* Kh, const __half* Vt,
    int b, int g, int kt, int tid)
{
    const int tk0 = b * SS + kt * 64;
    const size_t vrow0 = (size_t)((b * NKV + g) * HD) * SS;
    #pragma unroll 8
    for (int c = tid; c < 2048; c += 256) {
        if (c < 1024) {
            int r = c >> 4, sg = c & 15, half = sg >> 3, sgi = sg & 7;
            const void* src = Kh + (size_t)(tk0 + r) * KDIM + g * HD + half * 64 + sgi * 8;
            uint32_t dst = st + half * 8192 + sw128(r * 128 + sgi * 16);
            cp_async16(dst, src);
        } else {
            int idx = c - 1024;
            int d = idx >> 3, sg = idx & 7;
            const void* src = Vt + vrow0 + (size_t)d * SS + kt * 64 + sg * 8;
            uint32_t dst = st + 16384 + sw128(d * 128 + sg * 16);
            cp_async16(dst, src);
        }
    }
    CP_COMMIT();
}

__global__ __launch_bounds__(256, 1) void attn_mma(
    const __half* __restrict__ Qh, const __half* __restrict__ Ql,
    const __half* __restrict__ Kh, const __half* __restrict__ Vt,
    __half* __restrict__ Oh, __half* __restrict__ Ol)
{
    extern __shared__ char smc[];
    const uint32_t sb = smem_u32(smc);
    const int tid = threadIdx.x, wid = tid >> 5, lane = tid & 31;
    const int bid = blockIdx.x;
    const int qb = 15 - (bid >> 6);     // heavy-first
    const int bh = bid & 63;
    const int b = bh >> 5, h = bh & 31, g = h >> 2;
    const int tok0 = b * SS + qb * 128;
    const int KT = 2 * qb + 2;
    const float SCL = 0.08838834764831845f * 1.4426950408889634f;

    // Q load: hi/lo x 128 rows x 16 chunks = 4096 chunks (group 0, with kv(0))
    #pragma unroll 4
    for (int c = tid; c < 4096; c += 256) {
        int hl = c >> 11, cc = c & 2047;
        int r = cc >> 4, sg = cc & 15, half = sg >> 3, sgi = sg & 7;
        const __half* base = hl ? Ql : Qh;
        const void* src = base + (size_t)(tok0 + r) * QDIM + h * HD + half * 64 + sgi * 8;
        uint32_t dst = sb + hl * 32768 + half * 16384 + sw128(r * 128 + sgi * 16);
        cp_async16(dst, src);
    }
    attn_load_kv(sb + 65536, Kh, Vt, b, g, 0, tid);             // stage 0 (commit)
    attn_load_kv(sb + 65536 + 32768, Kh, Vt, b, g, 1, tid);     // stage 1 (KT>=2 always)

    float o[16][4];
    #pragma unroll
    for (int nd = 0; nd < 16; nd++)
        #pragma unroll
        for (int e = 0; e < 4; e++) o[nd][e] = 0.f;
    float m0 = -1e30f, m1 = -1e30f, l0 = 0.f, l1 = 0.f;

    const int qg0 = qb * 128 + wid * 16 + (lane >> 2);
    const int qg1 = qg0 + 8;

    int bi = 0, ni = 2;   // stage buffer trackers

    for (int kt = 0; kt < KT; kt++) {
        if (kt + 1 < KT) { CP_WAIT1(); } else { CP_WAIT0(); }
        __syncthreads();
        if (kt + 2 < KT)
            attn_load_kv(sb + 65536 + ni * 32768, Kh, Vt, b, g, kt + 2, tid);

        const uint32_t st = sb + 65536 + bi * 32768;
        bi = (bi == 2) ? 0 : bi + 1;
        ni = (ni == 2) ? 0 : ni + 1;
        const bool skip = kt * 64 > qb * 128 + wid * 16 + 15;

        if (!skip) {
            float s[8][4];
            #pragma unroll
            for (int nj = 0; nj < 8; nj++)
                #pragma unroll
                for (int e = 0; e < 4; e++) s[nj][e] = 0.f;

            #pragma unroll
            for (int k16 = 0; k16 < 8; k16++) {
                const int half = k16 >> 2;
                const int cb = (k16 & 3) * 32 + (lane >> 4) * 16;
                const uint32_t qoff = sw128((wid * 16 + (lane & 15)) * 128 + cb);
                uint32_t ah[4], al[4];
                LDSM4(ah, sb + half * 16384 + qoff);
                LDSM4(al, sb + 32768 + half * 16384 + qoff);
                uint32_t bhf[4][4];
                #pragma unroll
                for (int c = 0; c < 4; c++) {
                    const uint32_t koff = sw128((c * 16 + (lane & 15)) * 128 + cb);
                    LDSM4(bhf[c], st + half * 8192 + koff);
                }
                #pragma unroll
                for (int nj = 0; nj < 8; nj++) {
                    const int np = nj >> 1, h2 = nj & 1;
                    MMAH16816(s[nj], ah, bhf[np][h2], bhf[np][2 + h2]);
                }
                #pragma unroll
                for (int nj = 0; nj < 8; nj++) {
                    const int np = nj >> 1, h2 = nj & 1;
                    MMAH16816(s[nj], al, bhf[np][h2], bhf[np][2 + h2]);
                }
            }

            const bool domask = (kt * 64 + 63) > qg0;
            #pragma unroll
            for (int nj = 0; nj < 8; nj++) {
                #pragma unroll
                for (int e = 0; e < 4; e++) s[nj][e] *= SCL;
                if (domask) {
                    const int kc = kt * 64 + nj * 8 + (lane & 3) * 2;
                    if (kc     > qg0) s[nj][0] = -1e30f;
                    if (kc + 1 > qg0) s[nj][1] = -1e30f;
                    if (kc     > qg1) s[nj][2] = -1e30f;
                    if (kc + 1 > qg1) s[nj][3] = -1e30f;
                }
            }
            float mx0 = -1e30f, mx1 = -1e30f;
            #pragma unroll
            for (int nj = 0; nj < 8; nj++) {
                mx0 = fmaxf(mx0, fmaxf(s[nj][0], s[nj][1]));
                mx1 = fmaxf(mx1, fmaxf(s[nj][2], s[nj][3]));
            }
            mx0 = fmaxf(mx0, __shfl_xor_sync(0xffffffffu, mx0, 1));
            mx0 = fmaxf(mx0, __shfl_xor_sync(0xffffffffu, mx0, 2));
            mx1 = fmaxf(mx1, __shfl_xor_sync(0xffffffffu, mx1, 1));
            mx1 = fmaxf(mx1, __shfl_xor_sync(0xffffffffu, mx1, 2));
            const float nm0 = fmaxf(m0, mx0), nm1 = fmaxf(m1, mx1);
            const float c0 = exp2a(m0 - nm0), c1 = exp2a(m1 - nm1);
            float rs0 = 0.f, rs1 = 0.f;
            #pragma unroll
            for (int nj = 0; nj < 8; nj++) {
                s[nj][0] = exp2a(s[nj][0] - nm0);
                s[nj][1] = exp2a(s[nj][1] - nm0);
                s[nj][2] = exp2a(s[nj][2] - nm1);
                s[nj][3] = exp2a(s[nj][3] - nm1);
                rs0 += s[nj][0] + s[nj][1];
                rs1 += s[nj][2] + s[nj][3];
            }
            rs0 += __shfl_xor_sync(0xffffffffu, rs0, 1);
            rs0 += __shfl_xor_sync(0xffffffffu, rs0, 2);
            rs1 += __shfl_xor_sync(0xffffffffu, rs1, 1);
            rs1 += __shfl_xor_sync(0xffffffffu, rs1, 2);
            m0 = nm0; m1 = nm1;
            l0 = l0 * c0 + rs0;
            l1 = l1 * c1 + rs1;
            #pragma unroll
            for (int nd = 0; nd < 16; nd++) {
                o[nd][0] *= c0; o[nd][1] *= c0;
                o[nd][2] *= c1; o[nd][3] *= c1;
            }

            // P*V: P exact fp16 hi/lo in registers, V single fp16
            #pragma unroll
            for (int j2 = 0; j2 < 4; j2++) {
                const int n0 = 2 * j2, n1 = 2 * j2 + 1;
                uint32_t aPh[4], aPl[4];
                __half2 t0 = __floats2half2_rn(s[n0][0], s[n0][1]);
                __half2 t1 = __floats2half2_rn(s[n0][2], s[n0][3]);
                __half2 t2 = __floats2half2_rn(s[n1][0], s[n1][1]);
                __half2 t3 = __floats2half2_rn(s[n1][2], s[n1][3]);
                aPh[0] = *(uint32_t*)&t0; aPh[1] = *(uint32_t*)&t1;
                aPh[2] = *(uint32_t*)&t2; aPh[3] = *(uint32_t*)&t3;
                __half2 u0 = __floats2half2_rn(s[n0][0] - __low2float(t0),
                                               s[n0][1] - __high2float(t0));
                __half2 u1 = __floats2half2_rn(s[n0][2] - __low2float(t1),
                                               s[n0][3] - __high2float(t1));
                __half2 u2 = __floats2half2_rn(s[n1][0] - __low2float(t2),
                                               s[n1][1] - __high2float(t2));
                __half2 u3 = __floats2half2_rn(s[n1][2] - __low2float(t3),
                                               s[n1][3] - __high2float(t3));
                aPl[0] = *(uint32_t*)&u0; aPl[1] = *(uint32_t*)&u1;
                aPl[2] = *(uint32_t*)&u2; aPl[3] = *(uint32_t*)&u3;

                #pragma unroll
                for (int c = 0; c < 8; c++) {
                    const uint32_t voff = sw128((c * 16 + (lane & 15)) * 128 + j2 * 32 + (lane >> 4) * 16);
                    uint32_t vh[4];
                    LDSM4(vh, st + 16384 + voff);
                    MMAH16816(o[2 * c],     aPh, vh[0], vh[2]);
                    MMAH16816(o[2 * c + 1], aPh, vh[1], vh[3]);
                    MMAH16816(o[2 * c],     aPl, vh[0], vh[2]);
                    MMAH16816(o[2 * c + 1], aPl, vh[1], vh[3]);
                }
            }
        }
    }

    // epilogue: normalize, split to fp16 hi/lo for the Wo fp16 GEMM
    const float il0 = 1.f / l0, il1 = 1.f / l1;
    const int row0g = tok0 + wid * 16 + (lane >> 2);
    #pragma unroll
    for (int nd = 0; nd < 16; nd++) {
        const int col = h * HD + nd * 8 + (lane & 3) * 2;
        float v00 = o[nd][0] * il0, v01 = o[nd][1] * il0;
        float v10 = o[nd][2] * il1, v11 = o[nd][3] * il1;
        __half2 h0 = __floats2half2_rn(v00, v01);
        __half2 h1 = __floats2half2_rn(v10, v11);
        __half2 q0 = __floats2half2_rn(v00 - __low2float(h0), v01 - __high2float(h0));
        __half2 q1 = __floats2half2_rn(v10 - __low2float(h1), v11 - __high2float(h1));
        *(uint32_t*)(Oh + (size_t)row0g * QDIM + col)       = *(uint32_t*)&h0;
        *(uint32_t*)(Ol + (size_t)row0g * QDIM + col)       = *(uint32_t*)&q0;
        *(uint32_t*)(Oh + (size_t)(row0g + 8) * QDIM + col) = *(uint32_t*)&h1;
        *(uint32_t*)(Ol + (size_t)(row0g + 8) * QDIM + col) = *(uint32_t*)&q1;
    }
}

// ---------------- launcher ---------------------------------------------------
extern "C" void kernel_launch(void* const* d_in, const int* in_sizes, int n_in,
                              void* d_out, int out_size)
{
    const float* x    = (const float*)d_in[0];
    const float* cosT = (const float*)d_in[1];
    const float* sinT = (const float*)d_in[2];
    const float* Wq   = (const float*)d_in[3];
    const float* Wk   = (const float*)d_in[4];
    const float* Wv   = (const float*)d_in[5];
    const float* Wo   = (const float*)d_in[6];
    float* out = (float*)d_out;

    float *Q, *K, *V;
    __half *xh, *xl, *Wqh, *Wkh, *Wvh, *Woh, *Ah, *Al;
    __half *Qah, *Qal, *Kah, *Vt;
    cudaGetSymbolAddress((void**)&Q, g_Q);
    cudaGetSymbolAddress((void**)&K, g_K);
    cudaGetSymbolAddress((void**)&V, g_V);
    cudaGetSymbolAddress((void**)&xh, g_xh);
    cudaGetSymbolAddress((void**)&xl, g_xl);
    cudaGetSymbolAddress((void**)&Wqh, g_Wqh);
    cudaGetSymbolAddress((void**)&Wkh, g_Wkh);
    cudaGetSymbolAddress((void**)&Wvh, g_Wvh);
    cudaGetSymbolAddress((void**)&Woh, g_Woh);
    cudaGetSymbolAddress((void**)&Ah, g_Ah);
    cudaGetSymbolAddress((void**)&Al, g_Al);
    cudaGetSymbolAddress((void**)&Qah, g_Qah);
    cudaGetSymbolAddress((void**)&Qal, g_Qal);
    cudaGetSymbolAddress((void**)&Kah, g_Kah);
    cudaGetSymbolAddress((void**)&Vt, g_Vt);

    cudaFuncSetAttribute(gemm_fp16x2, cudaFuncAttributeMaxDynamicSharedMemorySize, GSMEM_BYTES);
    cudaFuncSetAttribute(attn_mma, cudaFuncAttributeMaxDynamicSharedMemorySize, ASMEM_BYTES);

    // zero-init split-K targets (exactly 2 atomic contributors -> deterministic)
    cudaMemsetAsync(Q, 0, (size_t)NT * QDIM * sizeof(float));
    cudaMemsetAsync(out, 0, (size_t)NT * DIM * sizeof(float));

    // conversions
    split_rows_h<<<(NT * DIM / 4 + 255) / 256, 256>>>(x, xh, xl, NT * DIM / 4);
    transpose_h<<<dim3(QDIM / 64, DIM / 64), 256>>>(Wq, Wqh, DIM, QDIM);
    transpose_h<<<dim3(KDIM / 64, DIM / 64), 256>>>(Wk, Wkh, DIM, KDIM);
    transpose_h<<<dim3(KDIM / 64, DIM / 64), 256>>>(Wv, Wvh, DIM, KDIM);
    transpose_h<<<dim3(DIM / 64, QDIM / 64), 256>>>(Wo, Woh, QDIM, DIM);

    // QKV projections (fp16 2-term HMMA; Q with split-K=2)
    gemm_fp16x2<<<dim3(QDIM / 256, NT / 128, 2), 256, GSMEM_BYTES>>>(xh, xl, Wqh, Q, NT, QDIM, DIM);
    gemm_fp16x2<<<dim3(KDIM / 256, NT / 128, 1), 256, GSMEM_BYTES>>>(xh, xl, Wkh, K, NT, KDIM, DIM);
    gemm_fp16x2<<<dim3(KDIM / 256, NT / 128, 1), 256, GSMEM_BYTES>>>(xh, xl, Wvh, V, NT, KDIM, DIM);

    // RoPE + fp16 operands for attention
    rope_q_h<<<(NT * NH * 32 + 255) / 256, 256>>>(Q, cosT, sinT, Qah, Qal);
    rope_k_h<<<(NT * NKV * 32 + 255) / 256, 256>>>(K, cosT, sinT, Kah);
    v_t_h<<<dim3(KDIM / 64, NT / 64), 256>>>(V, Vt);

    // fp16 2-term flash attention (3-stage KV pipeline)
    attn_mma<<<1024, 256, ASMEM_BYTES>>>(Qah, Qal, Kah, Vt, Ah, Al);

    // Output projection (fp16 2-term, split-K=2)
    gemm_fp16x2<<<dim3(DIM / 256, NT / 128, 2), 256, GSMEM_BYTES>>>(Ah, Al, Woh, out, NT, DIM, QDIM);
}

// round 14
// speedup vs baseline: 1.0370x; 1.0370x over previous
#include <cuda_runtime.h>
#include <cuda_bf16.h>
#include <cuda_fp16.h>
#include <math.h>
#include <stdint.h>

// Problem constants
#define BB   2
#define SS   2048
#define DIM  4096
#define NH   32
#define NKV  8
#define HD   128
#define NT   (BB*SS)          // 4096 tokens
#define QDIM (NH*HD)          // 4096
#define KDIM (NKV*HD)         // 1024

// ---------------- scratch (device globals; no allocation allowed) ----------
__device__ float g_Q[2 * NT * QDIM];     // two split-K partial buffers
__device__ __half g_xh[NT * DIM];
__device__ __half g_xl[NT * DIM];
__device__ __half g_Wqh[QDIM * DIM];     // transposed [N][K]
__device__ __half g_Wkh[KDIM * DIM];
__device__ __half g_Wvh[KDIM * DIM];
__device__ __half g_Woh[DIM * QDIM];
__device__ __half g_Ah[NT * QDIM];       // attention out hi (fp16)
__device__ __half g_Al[NT * QDIM];       // attention out lo (fp16)
__device__ __half g_Qah[NT * QDIM];      // Q hi (exact split)
__device__ __half g_Qal[NT * QDIM];      // Q lo
__device__ __half g_Kah[NT * KDIM];      // K single fp16 (RoPE'd)
__device__ __half g_Vt[BB * NKV * HD * SS];  // V transposed [b][g][d][s]

// ======================= PTX helpers =======================
__device__ __forceinline__ uint32_t smem_u32(const void* p) {
    uint32_t a;
    asm("{ .reg .u64 t; cvta.to.shared.u64 t, %1; cvt.u32.u64 %0, t; }" : "=r"(a) : "l"(p));
    return a;
}
__device__ __forceinline__ void cp_async16(uint32_t dst, const void* src) {
    asm volatile("cp.async.cg.shared.global [%0], [%1], 16;" :: "r"(dst), "l"(src));
}
#define CP_COMMIT() asm volatile("cp.async.commit_group;" ::: "memory")
#define CP_WAIT0()  asm volatile("cp.async.wait_group 0;" ::: "memory")

__device__ __forceinline__ uint32_t sw128(uint32_t b) { return b ^ ((b >> 3) & 0x70); }

__device__ __forceinline__ float exp2a(float x) {
    float r;
    asm("ex2.approx.f32 %0, %1;" : "=f"(r) : "f"(x));
    return r;
}

#define LDSM4(r, addr) \
    asm volatile("ldmatrix.sync.aligned.m8n8.x4.shared.b16 {%0,%1,%2,%3}, [%4];" \
        : "=r"((r)[0]), "=r"((r)[1]), "=r"((r)[2]), "=r"((r)[3]) : "r"(addr))

#define MMAH16816(c, a, b0, b1) \
    asm volatile("mma.sync.aligned.m16n8k16.row.col.f32.f16.f16.f32 " \
        "{%0,%1,%2,%3}, {%4,%5,%6,%7}, {%8,%9}, {%0,%1,%2,%3};" \
        : "+f"((c)[0]), "+f"((c)[1]), "+f"((c)[2]), "+f"((c)[3]) \
        : "r"((a)[0]), "r"((a)[1]), "r"((a)[2]), "r"((a)[3]), "r"(b0), "r"(b1))

// =============== fp16 2-term HMMA GEMM core (2-stage, 128x256 tile) =========
#define GSMEM_BYTES (2 * 65536)

__device__ __forceinline__ void load_stage_part(
    uint32_t buf, const __half* Ah, const __half* Al, const __half* Bh,
    int row0, int col0, int K, int kchunk, int tid, int part)
{
    #pragma unroll
    for (int j = 0; j < 4; j++) {
        const int c = tid + part * 1024 + j * 256;
        if (c < 1024) {
            const int r = c >> 3, sg = c & 7;
            const uint32_t dst = buf + sw128(r * 128 + sg * 16);
            cp_async16(dst, Ah + (size_t)(row0 + r) * K + kchunk * 64 + sg * 8);
        } else if (c < 2048) {
            const int idx = c - 1024;
            const int r = idx >> 3, sg = idx & 7;
            const uint32_t dst = buf + 16384 + sw128(r * 128 + sg * 16);
            cp_async16(dst, Al + (size_t)(row0 + r) * K + kchunk * 64 + sg * 8);
        } else {
            const int idx = c - 2048;
            const int r = idx >> 3, sg = idx & 7;      // r 0..255
            const uint32_t dst = buf + 32768 + sw128(r * 128 + sg * 16);
            cp_async16(dst, Bh + (size_t)(col0 + r) * K + kchunk * 64 + sg * 8);
        }
    }
}

// mainloop shared by all GEMM variants; leaves results in acc[4][8][4]
// NOTE: single-group-ahead pipeline -> the wait at loop head MUST be wait_group 0.
#define GEMM_MAINLOOP(Ah, Al, Bh, row0, col0, K, kb, KT)                        \
    {                                                                           \
        _Pragma("unroll")                                                       \
        for (int p = 0; p < 4; p++)                                             \
            load_stage_part(sb, Ah, Al, Bh, row0, col0, K, kb, tid, p);         \
        CP_COMMIT();                                                            \
        for (int it = 0; it < KT; it++) {                                       \
            const uint32_t buf = sb + (it & 1) * 65536;                         \
            const uint32_t nbuf = sb + ((it + 1) & 1) * 65536;                  \
            const bool more = (it + 1 < KT);                                    \
            CP_WAIT0();                                                         \
            __syncthreads();                                                    \
            const uint32_t aHb = buf;                                           \
            const uint32_t aLb = buf + 16384;                                   \
            const uint32_t bHb = buf + 32768;                                   \
            _Pragma("unroll")                                                   \
            for (int k16 = 0; k16 < 4; k16++) {                                 \
                if (more) {                                                     \
                    load_stage_part(nbuf, Ah, Al, Bh, row0, col0, K, kb + it + 1, tid, k16); \
                    if (k16 == 3) CP_COMMIT();                                  \
                }                                                               \
                const int colb = k16 * 32 + (lane >> 4) * 16;                   \
                uint32_t ahf[4][4], alf[4][4];                                  \
                _Pragma("unroll")                                               \
                for (int mi = 0; mi < 4; mi++) {                                \
                    const uint32_t off = sw128((wm0 + mi * 16 + (lane & 15)) * 128 + colb); \
                    LDSM4(ahf[mi], aHb + off);                                  \
                    LDSM4(alf[mi], aLb + off);                                  \
                }                                                               \
                _Pragma("unroll")                                               \
                for (int hb = 0; hb < 2; hb++) {                                \
                    uint32_t bh[2][4];                                          \
                    _Pragma("unroll")                                           \
                    for (int np = 0; np < 2; np++) {                            \
                        const uint32_t off =                                    \
                            sw128((wn0 + hb * 32 + np * 16 + (lane & 15)) * 128 + colb); \
                        LDSM4(bh[np], bHb + off);                               \
                    }                                                           \
                    _Pragma("unroll")                                           \
                    for (int mi = 0; mi < 4; mi++)                              \
                        _Pragma("unroll")                                       \
                        for (int nj = 0; nj < 4; nj++) {                        \
                            const int np = nj >> 1, hq = nj & 1;                \
                            MMAH16816(acc[mi][hb * 4 + nj], ahf[mi], bh[np][hq], bh[np][2 + hq]); \
                        }                                                       \
                    _Pragma("unroll")                                           \
                    for (int mi = 0; mi < 4; mi++)                              \
                        _Pragma("unroll")                                       \
                        for (int nj = 0; nj < 4; nj++) {                        \
                            const int np = nj >> 1, hq = nj & 1;                \
                            MMAH16816(acc[mi][hb * 4 + nj], alf[mi], bh[np][hq], bh[np][2 + hq]); \
                        }                                                       \
                }                                                               \
            }                                                                   \
        }                                                                       \
    }

// Generic GEMM: mode 0 = plain store; mode 1 = store to C + z*M*N (split buf)
__global__ __launch_bounds__(256, 1) void gemm_fp16x2(
    const __half* __restrict__ Ah, const __half* __restrict__ Al,
    const __half* __restrict__ Bh,
    float* __restrict__ C, int M, int N, int K, int mode)
{
    extern __shared__ char smc[];
    const uint32_t sb = smem_u32(smc);
    const int tid = threadIdx.x;
    const int wid = tid >> 5;
    const int lane = tid & 31;
    const int row0 = blockIdx.y * 128;
    const int col0 = blockIdx.x * 256;
    const int nz = gridDim.z;
    const int K2 = K / nz;
    const int kb = blockIdx.z * (K2 / 64);
    const int wm0 = (wid >> 2) * 64;
    const int wn0 = (wid & 3) * 64;

    float acc[4][8][4];
    #pragma unroll
    for (int i = 0; i < 4; i++)
        #pragma unroll
        for (int j = 0; j < 8; j++)
            #pragma unroll
            for (int r = 0; r < 4; r++) acc[i][j][r] = 0.f;

    const int KT = K2 / 64;
    GEMM_MAINLOOP(Ah, Al, Bh, row0, col0, K, kb, KT);

    float* Cz = (mode == 1) ? (C + (size_t)blockIdx.z * M * N) : C;
    #pragma unroll
    for (int mi = 0; mi < 4; mi++) {
        #pragma unroll
        for (int nj = 0; nj < 8; nj++) {
            const int row = row0 + wm0 + mi * 16 + (lane >> 2);
            const int col = col0 + wn0 + nj * 8 + (lane & 3) * 2;
            *(float2*)(Cz + (size_t)row * N + col)       = make_float2(acc[mi][nj][0], acc[mi][nj][1]);
            *(float2*)(Cz + (size_t)(row + 8) * N + col) = make_float2(acc[mi][nj][2], acc[mi][nj][3]);
        }
    }
}

// GEMM with atomic accumulation (for Wo split-K into zeroed out)
__global__ __launch_bounds__(256, 1) void gemm_fp16x2_atomic(
    const __half* __restrict__ Ah, const __half* __restrict__ Al,
    const __half* __restrict__ Bh,
    float* __restrict__ C, int M, int N, int K)
{
    extern __shared__ char smc[];
    const uint32_t sb = smem_u32(smc);
    const int tid = threadIdx.x;
    const int wid = tid >> 5;
    const int lane = tid & 31;
    const int row0 = blockIdx.y * 128;
    const int col0 = blockIdx.x * 256;
    const int nz = gridDim.z;
    const int K2 = K / nz;
    const int kb = blockIdx.z * (K2 / 64);
    const int wm0 = (wid >> 2) * 64;
    const int wn0 = (wid & 3) * 64;

    float acc[4][8][4];
    #pragma unroll
    for (int i = 0; i < 4; i++)
        #pragma unroll
        for (int j = 0; j < 8; j++)
            #pragma unroll
            for (int r = 0; r < 4; r++) acc[i][j][r] = 0.f;

    const int KT = K2 / 64;
    GEMM_MAINLOOP(Ah, Al, Bh, row0, col0, K, kb, KT);

    #pragma unroll
    for (int mi = 0; mi < 4; mi++) {
        #pragma unroll
        for (int nj = 0; nj < 8; nj++) {
            const int row = row0 + wm0 + mi * 16 + (lane >> 2);
            const int col = col0 + wn0 + nj * 8 + (lane & 3) * 2;
            float* p0 = C + (size_t)row * N + col;
            float* p1 = C + (size_t)(row + 8) * N + col;
            atomicAdd(p0,     acc[mi][nj][0]);
            atomicAdd(p0 + 1, acc[mi][nj][1]);
            atomicAdd(p1,     acc[mi][nj][2]);
            atomicAdd(p1 + 1, acc[mi][nj][3]);
        }
    }
}

// K-projection GEMM with fused RoPE epilogue -> Kah fp16 (nz=1 only)
__global__ __launch_bounds__(256, 1) void gemm_k_rope(
    const __half* __restrict__ Ah, const __half* __restrict__ Al,
    const __half* __restrict__ Bh,
    const float* __restrict__ cosT, const float* __restrict__ sinT,
    __half* __restrict__ Kout, int M, int N, int K)
{
    extern __shared__ char smc[];
    const uint32_t sb = smem_u32(smc);
    const int tid = threadIdx.x;
    const int wid = tid >> 5;
    const int lane = tid & 31;
    const int row0 = blockIdx.y * 128;
    const int col0 = blockIdx.x * 256;
    const int kb = 0;
    const int wm0 = (wid >> 2) * 64;
    const int wn0 = (wid & 3) * 64;

    float acc[4][8][4];
    #pragma unroll
    for (int i = 0; i < 4; i++)
        #pragma unroll
        for (int j = 0; j < 8; j++)
            #pragma unroll
            for (int r = 0; r < 4; r++) acc[i][j][r] = 0.f;

    const int KT = K / 64;
    GEMM_MAINLOOP(Ah, Al, Bh, row0, col0, K, kb, KT);

    // stage acc tile to smem fp32 [128][256] (128KB)
    __syncthreads();
    float* tile = (float*)smc;
    #pragma unroll
    for (int mi = 0; mi < 4; mi++) {
        #pragma unroll
        for (int nj = 0; nj < 8; nj++) {
            const int r = wm0 + mi * 16 + (lane >> 2);
            const int c = wn0 + nj * 8 + (lane & 3) * 2;
            *(float2*)&tile[r * 256 + c]       = make_float2(acc[mi][nj][0], acc[mi][nj][1]);
            *(float2*)&tile[(r + 8) * 256 + c] = make_float2(acc[mi][nj][2], acc[mi][nj][3]);
        }
    }
    __syncthreads();

    // rope + write: 8192 uint32 units (128 rows x 2 heads x 32 d-pairs)
    #pragma unroll 4
    for (int i = 0; i < 32; i++) {
        const int idx = tid + i * 256;
        const int r = idx >> 6;
        const int rest = idx & 63;
        const int head2 = rest >> 5;
        const int d = (rest & 31) * 2;
        const int tok = row0 + r;
        const int s = tok & (SS - 1);
        const int cbase = head2 * 128;
        float x0 = tile[r * 256 + cbase + d];
        float x1 = tile[r * 256 + cbase + d + 1];
        float y0 = tile[r * 256 + cbase + d + 64];
        float y1 = tile[r * 256 + cbase + d + 65];
        const float* cp = cosT + s * HD;
        const float* sp = sinT + s * HD;
        float r0 = x0 * cp[d]      - y0 * sp[d];
        float r1 = x1 * cp[d + 1]  - y1 * sp[d + 1];
        float r2 = y0 * cp[d + 64] + x0 * sp[d + 64];
        float r3 = y1 * cp[d + 65] + x1 * sp[d + 65];
        const int gcol = col0 + cbase;
        const int g = gcol >> 7;
        size_t o = (size_t)tok * KDIM + g * HD + d;
        __half hp[2]  = {__float2half_rn(r0), __float2half_rn(r1)};
        __half hp2[2] = {__float2half_rn(r2), __float2half_rn(r3)};
        *(uint32_t*)(Kout + o)      = *(uint32_t*)hp;
        *(uint32_t*)(Kout + o + 64) = *(uint32_t*)hp2;
    }
}

// V-projection GEMM with fused transpose epilogue -> Vt fp16 (nz=1 only)
#define VT_PAD 132
__global__ __launch_bounds__(256, 1) void gemm_v_t(
    const __half* __restrict__ Ah, const __half* __restrict__ Al,
    const __half* __restrict__ Bh,
    __half* __restrict__ Vt, int M, int N, int K)
{
    extern __shared__ char smc[];
    const uint32_t sb = smem_u32(smc);
    const int tid = threadIdx.x;
    const int wid = tid >> 5;
    const int lane = tid & 31;
    const int row0 = blockIdx.y * 128;
    const int col0 = blockIdx.x * 256;
    const int kb = 0;
    const int wm0 = (wid >> 2) * 64;
    const int wn0 = (wid & 3) * 64;

    float acc[4][8][4];
    #pragma unroll
    for (int i = 0; i < 4; i++)
        #pragma unroll
        for (int j = 0; j < 8; j++)
            #pragma unroll
            for (int r = 0; r < 4; r++) acc[i][j][r] = 0.f;

    const int KT = K / 64;
    GEMM_MAINLOOP(Ah, Al, Bh, row0, col0, K, kb, KT);

    // stage transposed fp16 tile [256][VT_PAD]
    __syncthreads();
    __half* ht = (__half*)smc;
    #pragma unroll
    for (int mi = 0; mi < 4; mi++) {
        #pragma unroll
        for (int nj = 0; nj < 8; nj++) {
            const int r = wm0 + mi * 16 + (lane >> 2);
            const int c = wn0 + nj * 8 + (lane & 3) * 2;
            ht[c * VT_PAD + r]           = __float2half_rn(acc[mi][nj][0]);
            ht[(c + 1) * VT_PAD + r]     = __float2half_rn(acc[mi][nj][1]);
            ht[c * VT_PAD + r + 8]       = __float2half_rn(acc[mi][nj][2]);
            ht[(c + 1) * VT_PAD + r + 8] = __float2half_rn(acc[mi][nj][3]);
        }
    }
    __syncthreads();

    // each thread owns one column; write 128 tokens (32 x uint2)
    const int gcol = col0 + tid;
    const int g = gcol >> 7;
    const int d = gcol & 127;
    const int b = row0 >> 11;
    const int sbase = row0 & (SS - 1);
    __half* dst = Vt + ((size_t)((b * NKV + g) * HD) + d) * SS + sbase;
    const __half* srcc = ht + tid * VT_PAD;
    #pragma unroll 8
    for (int i = 0; i < 32; i++)
        *(uint2*)(dst + i * 4) = *(const uint2*)(srcc + i * 4);
}

// =============== fp32 -> fp16 hi/lo split (row-major) ===========
__global__ void split_rows_h(const float* __restrict__ X,
                             __half* __restrict__ Xh,
                             __half* __restrict__ Xl, int total4)
{
    int i = blockIdx.x * blockDim.x + threadIdx.x;
    if (i >= total4) return;
    float4 v = *(const float4*)(X + (size_t)i * 4);
    __half h[4], l[4];
    float vv[4] = {v.x, v.y, v.z, v.w};
    #pragma unroll
    for (int j = 0; j < 4; j++) {
        h[j] = __float2half_rn(vv[j]);
        l[j] = __float2half_rn(vv[j] - __half2float(h[j]));
    }
    *(uint2*)(Xh + (size_t)i * 4) = *(uint2*)h;
    *(uint2*)(Xl + (size_t)i * 4) = *(uint2*)l;
}

// =============== transpose + fp16 quantize: W[K,N] fp32 -> T [N,K] fp16 =====
__global__ __launch_bounds__(256) void transpose_h(
    const float* __restrict__ W, __half* __restrict__ Th, int Kd, int Nd)
{
    __shared__ float t[64][65];
    const int n0 = blockIdx.x * 64, k0 = blockIdx.y * 64;
    const int tid = threadIdx.x;
    #pragma unroll
    for (int i = 0; i < 4; i++) {
        int it = tid + i * 256;
        int r = it >> 4;
        int c4 = (it & 15) * 4;
        float4 v = *(const float4*)(W + (size_t)(k0 + r) * Nd + n0 + c4);
        t[r][c4] = v.x; t[r][c4 + 1] = v.y; t[r][c4 + 2] = v.z; t[r][c4 + 3] = v.w;
    }
    __syncthreads();
    #pragma unroll
    for (int i = 0; i < 4; i++) {
        int it = tid + i * 256;
        int n = it >> 4;
        int kc = (it & 15) * 4;
        __half h[4];
        #pragma unroll
        for (int j = 0; j < 4; j++) h[j] = __float2half_rn(t[kc + j][n]);
        *(uint2*)(Th + (size_t)(n0 + n) * Kd + k0 + kc) = *(uint2*)h;
    }
}

// =============== RoPE + fp16 hi/lo split (Q), summing two split-K buffers ===
__global__ void rope_q_h(const float* __restrict__ Q0,
                         const float* __restrict__ cosT,
                         const float* __restrict__ sinT,
                         __half* __restrict__ Xh,
                         __half* __restrict__ Xl)
{
    int idx = blockIdx.x * blockDim.x + threadIdx.x;
    int total = NT * NH * 32;
    if (idx >= total) return;
    int j = idx & 31;
    int hh = (idx >> 5) % NH;
    int t = idx / (32 * NH);
    int s = t & (SS - 1);
    int d = 2 * j;

    const float* p0 = Q0 + (size_t)t * QDIM + hh * HD;
    const float* p1 = p0 + (size_t)NT * QDIM;
    float x0 = p0[d]      + p1[d];
    float x1 = p0[d + 1]  + p1[d + 1];
    float y0 = p0[d + 64] + p1[d + 64];
    float y1 = p0[d + 65] + p1[d + 65];
    const float* cp = cosT + s * HD;
    const float* sp = sinT + s * HD;
    float r0 = x0 * cp[d]      - y0 * sp[d];
    float r1 = x1 * cp[d + 1]  - y1 * sp[d + 1];
    float r2 = y0 * cp[d + 64] + x0 * sp[d + 64];
    float r3 = y1 * cp[d + 65] + x1 * sp[d + 65];

    size_t o0 = (size_t)t * QDIM + hh * HD + d;
    __half h0 = __float2half_rn(r0), h1 = __float2half_rn(r1);
    __half h2 = __float2half_rn(r2), h3 = __float2half_rn(r3);
    __half q0 = __float2half_rn(r0 - __half2float(h0));
    __half q1 = __float2half_rn(r1 - __half2float(h1));
    __half q2 = __float2half_rn(r2 - __half2float(h2));
    __half q3 = __float2half_rn(r3 - __half2float(h3));
    __half hp[2] = {h0, h1};  *(uint32_t*)(Xh + o0) = *(uint32_t*)hp;
    __half lp[2] = {q0, q1};  *(uint32_t*)(Xl + o0) = *(uint32_t*)lp;
    __half hp2[2] = {h2, h3}; *(uint32_t*)(Xh + o0 + 64) = *(uint32_t*)hp2;
    __half lp2[2] = {q2, q3}; *(uint32_t*)(Xl + o0 + 64) = *(uint32_t*)lp2;
}

// ---------------- fp16 2-term flash attention (causal, GQA, 2-stage KV) -----
// smem: Qh 32KB | Ql 32KB | 2 stages x (K 16KB + Vt 16KB) = 128KB
#define ASMEM_BYTES (131072)

__device__ __forceinline__ void attn_load_kv(
    uint32_t st, const __half* Kh, const __half* Vt,
    int b, int g, int kt, int tid)
{
    const int tk0 = b * SS + kt * 64;
    const size_t vrow0 = (size_t)((b * NKV + g) * HD) * SS;
    #pragma unroll 8
    for (int c = tid; c < 2048; c += 256) {
        if (c < 1024) {
            int r = c >> 4, sg = c & 15, half = sg >> 3, sgi = sg & 7;
            const void* src = Kh + (size_t)(tk0 + r) * KDIM + g * HD + half * 64 + sgi * 8;
            uint32_t dst = st + half * 8192 + sw128(r * 128 + sgi * 16);
            cp_async16(dst, src);
        } else {
            int idx = c - 1024;
            int d = idx >> 3, sg = idx & 7;
            const void* src = Vt + vrow0 + (size_t)d * SS + kt * 64 + sg * 8;
            uint32_t dst = st + 16384 + sw128(d * 128 + sg * 16);
            cp_async16(dst, src);
        }
    }
    CP_COMMIT();
}

__global__ __launch_bounds__(256, 1) void attn_mma(
    const __half* __restrict__ Qh, const __half* __restrict__ Ql,
    const __half* __restrict__ Kh, const __half* __restrict__ Vt,
    __half* __restrict__ Oh, __half* __restrict__ Ol)
{
    extern __shared__ char smc[];
    const uint32_t sb = smem_u32(smc);
    const int tid = threadIdx.x, wid = tid >> 5, lane = tid & 31;
    const int bid = blockIdx.x;
    const int qb = 15 - (bid >> 6);     // heavy-first
    const int bh = bid & 63;
    const int b = bh >> 5, h = bh & 31, g = h >> 2;
    const int tok0 = b * SS + qb * 128;
    const int KT = 2 * qb + 2;
    const float SCL = 0.08838834764831845f * 1.4426950408889634f;

    #pragma unroll 4
    for (int c = tid; c < 4096; c += 256) {
        int hl = c >> 11, cc = c & 2047;
        int r = cc >> 4, sg = cc & 15, half = sg >> 3, sgi = sg & 7;
        const __half* base = hl ? Ql : Qh;
        const void* src = base + (size_t)(tok0 + r) * QDIM + h * HD + half * 64 + sgi * 8;
        uint32_t dst = sb + hl * 32768 + half * 16384 + sw128(r * 128 + sgi * 16);
        cp_async16(dst, src);
    }
    attn_load_kv(sb + 65536, Kh, Vt, b, g, 0, tid);

    float o[16][4];
    #pragma unroll
    for (int nd = 0; nd < 16; nd++)
        #pragma unroll
        for (int e = 0; e < 4; e++) o[nd][e] = 0.f;
    float m0 = -1e30f, m1 = -1e30f, l0 = 0.f, l1 = 0.f;

    const int qg0 = qb * 128 + wid * 16 + (lane >> 2);
    const int qg1 = qg0 + 8;

    for (int kt = 0; kt < KT; kt++) {
        CP_WAIT0();
        __syncthreads();
        if (kt + 1 < KT)
            attn_load_kv(sb + 65536 + ((kt + 1) & 1) * 32768, Kh, Vt, b, g, kt + 1, tid);

        const uint32_t st = sb + 65536 + (kt & 1) * 32768;
        const bool skip = kt * 64 > qb * 128 + wid * 16 + 15;

        if (!skip) {
            float s[8][4];
            #pragma unroll
            for (int nj = 0; nj < 8; nj++)
                #pragma unroll
                for (int e = 0; e < 4; e++) s[nj][e] = 0.f;

            #pragma unroll
            for (int k16 = 0; k16 < 8; k16++) {
                const int half = k16 >> 2;
                const int cb = (k16 & 3) * 32 + (lane >> 4) * 16;
                const uint32_t qoff = sw128((wid * 16 + (lane & 15)) * 128 + cb);
                uint32_t ah[4], al[4];
                LDSM4(ah, sb + half * 16384 + qoff);
                LDSM4(al, sb + 32768 + half * 16384 + qoff);
                uint32_t bhf[4][4];
                #pragma unroll
                for (int c = 0; c < 4; c++) {
                    const uint32_t koff = sw128((c * 16 + (lane & 15)) * 128 + cb);
                    LDSM4(bhf[c], st + half * 8192 + koff);
                }
                #pragma unroll
                for (int nj = 0; nj < 8; nj++) {
                    const int np = nj >> 1, h2 = nj & 1;
                    MMAH16816(s[nj], ah, bhf[np][h2], bhf[np][2 + h2]);
                }
                #pragma unroll
                for (int nj = 0; nj < 8; nj++) {
                    const int np = nj >> 1, h2 = nj & 1;
                    MMAH16816(s[nj], al, bhf[np][h2], bhf[np][2 + h2]);
                }
            }

            const bool domask = (kt * 64 + 63) > qg0;
            #pragma unroll
            for (int nj = 0; nj < 8; nj++) {
                #pragma unroll
                for (int e = 0; e < 4; e++) s[nj][e] *= SCL;
                if (domask) {
                    const int kc = kt * 64 + nj * 8 + (lane & 3) * 2;
                    if (kc     > qg0) s[nj][0] = -1e30f;
                    if (kc + 1 > qg0) s[nj][1] = -1e30f;
                    if (kc     > qg1) s[nj][2] = -1e30f;
                    if (kc + 1 > qg1) s[nj][3] = -1e30f;
                }
            }
            float mx0 = -1e30f, mx1 = -1e30f;
            #pragma unroll
            for (int nj = 0; nj < 8; nj++) {
                mx0 = fmaxf(mx0, fmaxf(s[nj][0], s[nj][1]));
                mx1 = fmaxf(mx1, fmaxf(s[nj][2], s[nj][3]));
            }
            mx0 = fmaxf(mx0, __shfl_xor_sync(0xffffffffu, mx0, 1));
            mx0 = fmaxf(mx0, __shfl_xor_sync(0xffffffffu, mx0, 2));
            mx1 = fmaxf(mx1, __shfl_xor_sync(0xffffffffu, mx1, 1));
            mx1 = fmaxf(mx1, __shfl_xor_sync(0xffffffffu, mx1, 2));
            const float nm0 = fmaxf(m0, mx0), nm1 = fmaxf(m1, mx1);
            const float c0 = exp2a(m0 - nm0), c1 = exp2a(m1 - nm1);
            float rs0 = 0.f, rs1 = 0.f;
            #pragma unroll
            for (int nj = 0; nj < 8; nj++) {
                s[nj][0] = exp2a(s[nj][0] - nm0);
                s[nj][1] = exp2a(s[nj][1] - nm0);
                s[nj][2] = exp2a(s[nj][2] - nm1);
                s[nj][3] = exp2a(s[nj][3] - nm1);
                rs0 += s[nj][0] + s[nj][1];
                rs1 += s[nj][2] + s[nj][3];
            }
            rs0 += __shfl_xor_sync(0xffffffffu, rs0, 1);
            rs0 += __shfl_xor_sync(0xffffffffu, rs0, 2);
            rs1 += __shfl_xor_sync(0xffffffffu, rs1, 1);
            rs1 += __shfl_xor_sync(0xffffffffu, rs1, 2);
            m0 = nm0; m1 = nm1;
            l0 = l0 * c0 + rs0;
            l1 = l1 * c1 + rs1;
            #pragma unroll
            for (int nd = 0; nd < 16; nd++) {
                o[nd][0] *= c0; o[nd][1] *= c0;
                o[nd][2] *= c1; o[nd][3] *= c1;
            }

            #pragma unroll
            for (int j2 = 0; j2 < 4; j2++) {
                const int n0 = 2 * j2, n1 = 2 * j2 + 1;
                uint32_t aPh[4], aPl[4];
                __half2 t0 = __floats2half2_rn(s[n0][0], s[n0][1]);
                __half2 t1 = __floats2half2_rn(s[n0][2], s[n0][3]);
                __half2 t2 = __floats2half2_rn(s[n1][0], s[n1][1]);
                __half2 t3 = __floats2half2_rn(s[n1][2], s[n1][3]);
                aPh[0] = *(uint32_t*)&t0; aPh[1] = *(uint32_t*)&t1;
                aPh[2] = *(uint32_t*)&t2; aPh[3] = *(uint32_t*)&t3;
                __half2 u0 = __floats2half2_rn(s[n0][0] - __low2float(t0),
                                               s[n0][1] - __high2float(t0));
                __half2 u1 = __floats2half2_rn(s[n0][2] - __low2float(t1),
                                               s[n0][3] - __high2float(t1));
                __half2 u2 = __floats2half2_rn(s[n1][0] - __low2float(t2),
                                               s[n1][1] - __high2float(t2));
                __half2 u3 = __floats2half2_rn(s[n1][2] - __low2float(t3),
                                               s[n1][3] - __high2float(t3));
                aPl[0] = *(uint32_t*)&u0; aPl[1] = *(uint32_t*)&u1;
                aPl[2] = *(uint32_t*)&u2; aPl[3] = *(uint32_t*)&u3;

                #pragma unroll
                for (int c = 0; c < 8; c++) {
                    const uint32_t voff = sw128((c * 16 + (lane & 15)) * 128 + j2 * 32 + (lane >> 4) * 16);
                    uint32_t vh[4];
                    LDSM4(vh, st + 16384 + voff);
                    MMAH16816(o[2 * c],     aPh, vh[0], vh[2]);
                    MMAH16816(o[2 * c + 1], aPh, vh[1], vh[3]);
                    MMAH16816(o[2 * c],     aPl, vh[0], vh[2]);
                    MMAH16816(o[2 * c + 1], aPl, vh[1], vh[3]);
                }
            }
        }
    }

    const float il0 = 1.f / l0, il1 = 1.f / l1;
    const int row0g = tok0 + wid * 16 + (lane >> 2);
    #pragma unroll
    for (int nd = 0; nd < 16; nd++) {
        const int col = h * HD + nd * 8 + (lane & 3) * 2;
        float v00 = o[nd][0] * il0, v01 = o[nd][1] * il0;
        float v10 = o[nd][2] * il1, v11 = o[nd][3] * il1;
        __half2 h0 = __floats2half2_rn(v00, v01);
        __half2 h1 = __floats2half2_rn(v10, v11);
        __half2 q0 = __floats2half2_rn(v00 - __low2float(h0), v01 - __high2float(h0));
        __half2 q1 = __floats2half2_rn(v10 - __low2float(h1), v11 - __high2float(h1));
        *(uint32_t*)(Oh + (size_t)row0g * QDIM + col)       = *(uint32_t*)&h0;
        *(uint32_t*)(Ol + (size_t)row0g * QDIM + col)       = *(uint32_t*)&q0;
        *(uint32_t*)(Oh + (size_t)(row0g + 8) * QDIM + col) = *(uint32_t*)&h1;
        *(uint32_t*)(Ol + (size_t)(row0g + 8) * QDIM + col) = *(uint32_t*)&q1;
    }
}

// ---------------- launcher ---------------------------------------------------
extern "C" void kernel_launch(void* const* d_in, const int* in_sizes, int n_in,
                              void* d_out, int out_size)
{
    const float* x    = (const float*)d_in[0];
    const float* cosT = (const float*)d_in[1];
    const float* sinT = (const float*)d_in[2];
    const float* Wq   = (const float*)d_in[3];
    const float* Wk   = (const float*)d_in[4];
    const float* Wv   = (const float*)d_in[5];
    const float* Wo   = (const float*)d_in[6];
    float* out = (float*)d_out;

    float* Q;
    __half *xh, *xl, *Wqh, *Wkh, *Wvh, *Woh, *Ah, *Al;
    __half *Qah, *Qal, *Kah, *Vt;
    cudaGetSymbolAddress((void**)&Q, g_Q);
    cudaGetSymbolAddress((void**)&xh, g_xh);
    cudaGetSymbolAddress((void**)&xl, g_xl);
    cudaGetSymbolAddress((void**)&Wqh, g_Wqh);
    cudaGetSymbolAddress((void**)&Wkh, g_Wkh);
    cudaGetSymbolAddress((void**)&Wvh, g_Wvh);
    cudaGetSymbolAddress((void**)&Woh, g_Woh);
    cudaGetSymbolAddress((void**)&Ah, g_Ah);
    cudaGetSymbolAddress((void**)&Al, g_Al);
    cudaGetSymbolAddress((void**)&Qah, g_Qah);
    cudaGetSymbolAddress((void**)&Qal, g_Qal);
    cudaGetSymbolAddress((void**)&Kah, g_Kah);
    cudaGetSymbolAddress((void**)&Vt, g_Vt);

    cudaFuncSetAttribute(gemm_fp16x2, cudaFuncAttributeMaxDynamicSharedMemorySize, GSMEM_BYTES);
    cudaFuncSetAttribute(gemm_fp16x2_atomic, cudaFuncAttributeMaxDynamicSharedMemorySize, GSMEM_BYTES);
    cudaFuncSetAttribute(gemm_k_rope, cudaFuncAttributeMaxDynamicSharedMemorySize, GSMEM_BYTES);
    cudaFuncSetAttribute(gemm_v_t, cudaFuncAttributeMaxDynamicSharedMemorySize, GSMEM_BYTES);
    cudaFuncSetAttribute(attn_mma, cudaFuncAttributeMaxDynamicSharedMemorySize, ASMEM_BYTES);

    // zero-init only the Wo split-K target
    cudaMemsetAsync(out, 0, (size_t)NT * DIM * sizeof(float));

    // conversions
    split_rows_h<<<(NT * DIM / 4 + 255) / 256, 256>>>(x, xh, xl, NT * DIM / 4);
    transpose_h<<<dim3(QDIM / 64, DIM / 64), 256>>>(Wq, Wqh, DIM, QDIM);
    transpose_h<<<dim3(KDIM / 64, DIM / 64), 256>>>(Wk, Wkh, DIM, KDIM);
    transpose_h<<<dim3(KDIM / 64, DIM / 64), 256>>>(Wv, Wvh, DIM, KDIM);
    transpose_h<<<dim3(DIM / 64, QDIM / 64), 256>>>(Wo, Woh, QDIM, DIM);

    // Q projection: split-K=2 into two plain-store buffers (no memset/atomics)
    gemm_fp16x2<<<dim3(QDIM / 256, NT / 128, 2), 256, GSMEM_BYTES>>>(xh, xl, Wqh, Q, NT, QDIM, DIM, 1);
    // K projection with fused RoPE -> Kah
    gemm_k_rope<<<dim3(KDIM / 256, NT / 128, 1), 256, GSMEM_BYTES>>>(xh, xl, Wkh, cosT, sinT, Kah, NT, KDIM, DIM);
    // V projection with fused transpose -> Vt
    gemm_v_t<<<dim3(KDIM / 256, NT / 128, 1), 256, GSMEM_BYTES>>>(xh, xl, Wvh, Vt, NT, KDIM, DIM);

    // Q: sum split buffers + RoPE + fp16 split
    rope_q_h<<<(NT * NH * 32 + 255) / 256, 256>>>(Q, cosT, sinT, Qah, Qal);

    // fp16 2-term flash attention (2-stage KV pipeline)
    attn_mma<<<1024, 256, ASMEM_BYTES>>>(Qah, Qal, Kah, Vt, Ah, Al);

    // Output projection (fp16 2-term, split-K=2, atomic into zeroed out)
    gemm_fp16x2_atomic<<<dim3(DIM / 256, NT / 128, 2), 256, GSMEM_BYTES>>>(Ah, Al, Woh, out, NT, DIM, QDIM);
}

// round 15
// speedup vs baseline: 1.2007x; 1.1579x over previous
#include <cuda_runtime.h>
#include <cuda_bf16.h>
#include <cuda_fp16.h>
#include <math.h>
#include <stdint.h>

// Problem constants
#define BB   2
#define SS   2048
#define DIM  4096
#define NH   32
#define NKV  8
#define HD   128
#define NT   (BB*SS)          // 4096 tokens
#define QDIM (NH*HD)          // 4096
#define KDIM (NKV*HD)         // 1024

// ---------------- scratch (device globals; no allocation allowed) ----------
__device__ float g_Q[2 * NT * QDIM];     // two split-K partial buffers
__device__ __half g_xh[NT * DIM];
__device__ __half g_xl[NT * DIM];
__device__ __half g_Wqh[QDIM * DIM];     // transposed [N][K]
__device__ __half g_Wkh[KDIM * DIM];
__device__ __half g_Wvh[KDIM * DIM];
__device__ __half g_Woh[DIM * QDIM];
__device__ __half g_Ah[NT * QDIM];       // attention out (fp16, single)
__device__ __half g_Qah[NT * QDIM];      // Q hi (exact split)
__device__ __half g_Qal[NT * QDIM];      // Q lo
__device__ __half g_Kah[NT * KDIM];      // K single fp16 (RoPE'd)
__device__ __half g_Vt[BB * NKV * HD * SS];  // V transposed [b][g][d][s]

// ======================= PTX helpers =======================
__device__ __forceinline__ uint32_t smem_u32(const void* p) {
    uint32_t a;
    asm("{ .reg .u64 t; cvta.to.shared.u64 t, %1; cvt.u32.u64 %0, t; }" : "=r"(a) : "l"(p));
    return a;
}
__device__ __forceinline__ void cp_async16(uint32_t dst, const void* src) {
    asm volatile("cp.async.cg.shared.global [%0], [%1], 16;" :: "r"(dst), "l"(src));
}
#define CP_COMMIT() asm volatile("cp.async.commit_group;" ::: "memory")
#define CP_WAIT0()  asm volatile("cp.async.wait_group 0;" ::: "memory")

__device__ __forceinline__ uint32_t sw128(uint32_t b) { return b ^ ((b >> 3) & 0x70); }

__device__ __forceinline__ float exp2a(float x) {
    float r;
    asm("ex2.approx.f32 %0, %1;" : "=f"(r) : "f"(x));
    return r;
}

#define LDSM4(r, addr) \
    asm volatile("ldmatrix.sync.aligned.m8n8.x4.shared.b16 {%0,%1,%2,%3}, [%4];" \
        : "=r"((r)[0]), "=r"((r)[1]), "=r"((r)[2]), "=r"((r)[3]) : "r"(addr))

#define MMAH16816(c, a, b0, b1) \
    asm volatile("mma.sync.aligned.m16n8k16.row.col.f32.f16.f16.f32 " \
        "{%0,%1,%2,%3}, {%4,%5,%6,%7}, {%8,%9}, {%0,%1,%2,%3};" \
        : "+f"((c)[0]), "+f"((c)[1]), "+f"((c)[2]), "+f"((c)[3]) \
        : "r"((a)[0]), "r"((a)[1]), "r"((a)[2]), "r"((a)[3]), "r"(b0), "r"(b1))

// =============== fp16 2-term HMMA GEMM core (2-stage, 128x256 tile) =========
#define GSMEM_BYTES (2 * 65536)

__device__ __forceinline__ void load_stage_part(
    uint32_t buf, const __half* Ah, const __half* Al, const __half* Bh,
    int row0, int col0, int K, int kchunk, int tid, int part)
{
    #pragma unroll
    for (int j = 0; j < 4; j++) {
        const int c = tid + part * 1024 + j * 256;
        if (c < 1024) {
            const int r = c >> 3, sg = c & 7;
            const uint32_t dst = buf + sw128(r * 128 + sg * 16);
            cp_async16(dst, Ah + (size_t)(row0 + r) * K + kchunk * 64 + sg * 8);
        } else if (c < 2048) {
            const int idx = c - 1024;
            const int r = idx >> 3, sg = idx & 7;
            const uint32_t dst = buf + 16384 + sw128(r * 128 + sg * 16);
            cp_async16(dst, Al + (size_t)(row0 + r) * K + kchunk * 64 + sg * 8);
        } else {
            const int idx = c - 2048;
            const int r = idx >> 3, sg = idx & 7;      // r 0..255
            const uint32_t dst = buf + 32768 + sw128(r * 128 + sg * 16);
            cp_async16(dst, Bh + (size_t)(col0 + r) * K + kchunk * 64 + sg * 8);
        }
    }
}

// 2-term mainloop; results in acc[4][8][4].
// single-group-ahead pipeline -> wait at loop head MUST be wait_group 0.
#define GEMM_MAINLOOP(Ah, Al, Bh, row0, col0, K, kb, KT)                        \
    {                                                                           \
        _Pragma("unroll")                                                       \
        for (int p = 0; p < 4; p++)                                             \
            load_stage_part(sb, Ah, Al, Bh, row0, col0, K, kb, tid, p);         \
        CP_COMMIT();                                                            \
        for (int it = 0; it < KT; it++) {                                       \
            const uint32_t buf = sb + (it & 1) * 65536;                         \
            const uint32_t nbuf = sb + ((it + 1) & 1) * 65536;                  \
            const bool more = (it + 1 < KT);                                    \
            CP_WAIT0();                                                         \
            __syncthreads();                                                    \
            const uint32_t aHb = buf;                                           \
            const uint32_t aLb = buf + 16384;                                   \
            const uint32_t bHb = buf + 32768;                                   \
            _Pragma("unroll")                                                   \
            for (int k16 = 0; k16 < 4; k16++) {                                 \
                if (more) {                                                     \
                    load_stage_part(nbuf, Ah, Al, Bh, row0, col0, K, kb + it + 1, tid, k16); \
                    if (k16 == 3) CP_COMMIT();                                  \
                }                                                               \
                const int colb = k16 * 32 + (lane >> 4) * 16;                   \
                uint32_t ahf[4][4], alf[4][4];                                  \
                _Pragma("unroll")                                               \
                for (int mi = 0; mi < 4; mi++) {                                \
                    const uint32_t off = sw128((wm0 + mi * 16 + (lane & 15)) * 128 + colb); \
                    LDSM4(ahf[mi], aHb + off);                                  \
                    LDSM4(alf[mi], aLb + off);                                  \
                }                                                               \
                _Pragma("unroll")                                               \
                for (int hb = 0; hb < 2; hb++) {                                \
                    uint32_t bh[2][4];                                          \
                    _Pragma("unroll")                                           \
                    for (int np = 0; np < 2; np++) {                            \
                        const uint32_t off =                                    \
                            sw128((wn0 + hb * 32 + np * 16 + (lane & 15)) * 128 + colb); \
                        LDSM4(bh[np], bHb + off);                               \
                    }                                                           \
                    _Pragma("unroll")                                           \
                    for (int mi = 0; mi < 4; mi++)                              \
                        _Pragma("unroll")                                       \
                        for (int nj = 0; nj < 4; nj++) {                        \
                            const int np = nj >> 1, hq = nj & 1;                \
                            MMAH16816(acc[mi][hb * 4 + nj], ahf[mi], bh[np][hq], bh[np][2 + hq]); \
                        }                                                       \
                    _Pragma("unroll")                                           \
                    for (int mi = 0; mi < 4; mi++)                              \
                        _Pragma("unroll")                                       \
                        for (int nj = 0; nj < 4; nj++) {                        \
                            const int np = nj >> 1, hq = nj & 1;                \
                            MMAH16816(acc[mi][hb * 4 + nj], alf[mi], bh[np][hq], bh[np][2 + hq]); \
                        }                                                       \
                }                                                               \
            }                                                                   \
        }                                                                       \
    }

// ---- 1-term variant (A single): stage = Ah 16KB | Bh 32KB = 48KB ----
#define GSMEM1_STAGE 49152
#define GSMEM1_BYTES (2 * GSMEM1_STAGE)

__device__ __forceinline__ void load_stage_part_1t(
    uint32_t buf, const __half* Ah, const __half* Bh,
    int row0, int col0, int K, int kchunk, int tid, int part)
{
    #pragma unroll
    for (int j = 0; j < 3; j++) {
        const int c = tid + part * 768 + j * 256;
        if (c < 1024) {
            const int r = c >> 3, sg = c & 7;
            const uint32_t dst = buf + sw128(r * 128 + sg * 16);
            cp_async16(dst, Ah + (size_t)(row0 + r) * K + kchunk * 64 + sg * 8);
        } else {
            const int idx = c - 1024;
            const int r = idx >> 3, sg = idx & 7;      // r 0..255
            const uint32_t dst = buf + 16384 + sw128(r * 128 + sg * 16);
            cp_async16(dst, Bh + (size_t)(col0 + r) * K + kchunk * 64 + sg * 8);
        }
    }
}

#define GEMM_MAINLOOP_1T(Ah, Bh, row0, col0, K, kb, KT)                         \
    {                                                                           \
        _Pragma("unroll")                                                       \
        for (int p = 0; p < 4; p++)                                             \
            load_stage_part_1t(sb, Ah, Bh, row0, col0, K, kb, tid, p);          \
        CP_COMMIT();                                                            \
        for (int it = 0; it < KT; it++) {                                       \
            const uint32_t buf = sb + (it & 1) * GSMEM1_STAGE;                  \
            const uint32_t nbuf = sb + ((it + 1) & 1) * GSMEM1_STAGE;           \
            const bool more = (it + 1 < KT);                                    \
            CP_WAIT0();                                                         \
            __syncthreads();                                                    \
            const uint32_t aHb = buf;                                           \
            const uint32_t bHb = buf + 16384;                                   \
            _Pragma("unroll")                                                   \
            for (int k16 = 0; k16 < 4; k16++) {                                 \
                if (more) {                                                     \
                    load_stage_part_1t(nbuf, Ah, Bh, row0, col0, K, kb + it + 1, tid, k16); \
                    if (k16 == 3) CP_COMMIT();                                  \
                }                                                               \
                const int colb = k16 * 32 + (lane >> 4) * 16;                   \
                uint32_t ahf[4][4];                                             \
                _Pragma("unroll")                                               \
                for (int mi = 0; mi < 4; mi++) {                                \
                    const uint32_t off = sw128((wm0 + mi * 16 + (lane & 15)) * 128 + colb); \
                    LDSM4(ahf[mi], aHb + off);                                  \
                }                                                               \
                _Pragma("unroll")                                               \
                for (int hb = 0; hb < 2; hb++) {                                \
                    uint32_t bh[2][4];                                          \
                    _Pragma("unroll")                                           \
                    for (int np = 0; np < 2; np++) {                            \
                        const uint32_t off =                                    \
                            sw128((wn0 + hb * 32 + np * 16 + (lane & 15)) * 128 + colb); \
                        LDSM4(bh[np], bHb + off);                               \
                    }                                                           \
                    _Pragma("unroll")                                           \
                    for (int mi = 0; mi < 4; mi++)                              \
                        _Pragma("unroll")                                       \
                        for (int nj = 0; nj < 4; nj++) {                        \
                            const int np = nj >> 1, hq = nj & 1;                \
                            MMAH16816(acc[mi][hb * 4 + nj], ahf[mi], bh[np][hq], bh[np][2 + hq]); \
                        }                                                       \
                }                                                               \
            }                                                                   \
        }                                                                       \
    }

// Generic 2-term GEMM: mode 0 = plain store; mode 1 = store to C + z*M*N
__global__ __launch_bounds__(256, 1) void gemm_fp16x2(
    const __half* __restrict__ Ah, const __half* __restrict__ Al,
    const __half* __restrict__ Bh,
    float* __restrict__ C, int M, int N, int K, int mode)
{
    extern __shared__ char smc[];
    const uint32_t sb = smem_u32(smc);
    const int tid = threadIdx.x;
    const int wid = tid >> 5;
    const int lane = tid & 31;
    const int row0 = blockIdx.y * 128;
    const int col0 = blockIdx.x * 256;
    const int nz = gridDim.z;
    const int K2 = K / nz;
    const int kb = blockIdx.z * (K2 / 64);
    const int wm0 = (wid >> 2) * 64;
    const int wn0 = (wid & 3) * 64;

    float acc[4][8][4];
    #pragma unroll
    for (int i = 0; i < 4; i++)
        #pragma unroll
        for (int j = 0; j < 8; j++)
            #pragma unroll
            for (int r = 0; r < 4; r++) acc[i][j][r] = 0.f;

    const int KT = K2 / 64;
    GEMM_MAINLOOP(Ah, Al, Bh, row0, col0, K, kb, KT);

    float* Cz = (mode == 1) ? (C + (size_t)blockIdx.z * M * N) : C;
    #pragma unroll
    for (int mi = 0; mi < 4; mi++) {
        #pragma unroll
        for (int nj = 0; nj < 8; nj++) {
            const int row = row0 + wm0 + mi * 16 + (lane >> 2);
            const int col = col0 + wn0 + nj * 8 + (lane & 3) * 2;
            *(float2*)(Cz + (size_t)row * N + col)       = make_float2(acc[mi][nj][0], acc[mi][nj][1]);
            *(float2*)(Cz + (size_t)(row + 8) * N + col) = make_float2(acc[mi][nj][2], acc[mi][nj][3]);
        }
    }
}

// 1-term GEMM with atomic accumulation (Wo split-K into zeroed out)
__global__ __launch_bounds__(256, 1) void gemm_fp16x1_atomic(
    const __half* __restrict__ Ah, const __half* __restrict__ Bh,
    float* __restrict__ C, int M, int N, int K)
{
    extern __shared__ char smc[];
    const uint32_t sb = smem_u32(smc);
    const int tid = threadIdx.x;
    const int wid = tid >> 5;
    const int lane = tid & 31;
    const int row0 = blockIdx.y * 128;
    const int col0 = blockIdx.x * 256;
    const int nz = gridDim.z;
    const int K2 = K / nz;
    const int kb = blockIdx.z * (K2 / 64);
    const int wm0 = (wid >> 2) * 64;
    const int wn0 = (wid & 3) * 64;

    float acc[4][8][4];
    #pragma unroll
    for (int i = 0; i < 4; i++)
        #pragma unroll
        for (int j = 0; j < 8; j++)
            #pragma unroll
            for (int r = 0; r < 4; r++) acc[i][j][r] = 0.f;

    const int KT = K2 / 64;
    GEMM_MAINLOOP_1T(Ah, Bh, row0, col0, K, kb, KT);

    #pragma unroll
    for (int mi = 0; mi < 4; mi++) {
        #pragma unroll
        for (int nj = 0; nj < 8; nj++) {
            const int row = row0 + wm0 + mi * 16 + (lane >> 2);
            const int col = col0 + wn0 + nj * 8 + (lane & 3) * 2;
            float* p0 = C + (size_t)row * N + col;
            float* p1 = C + (size_t)(row + 8) * N + col;
            atomicAdd(p0,     acc[mi][nj][0]);
            atomicAdd(p0 + 1, acc[mi][nj][1]);
            atomicAdd(p1,     acc[mi][nj][2]);
            atomicAdd(p1 + 1, acc[mi][nj][3]);
        }
    }
}

// K-projection GEMM with fused RoPE epilogue -> Kah fp16 (nz=1 only)
__global__ __launch_bounds__(256, 1) void gemm_k_rope(
    const __half* __restrict__ Ah, const __half* __restrict__ Al,
    const __half* __restrict__ Bh,
    const float* __restrict__ cosT, const float* __restrict__ sinT,
    __half* __restrict__ Kout, int M, int N, int K)
{
    extern __shared__ char smc[];
    const uint32_t sb = smem_u32(smc);
    const int tid = threadIdx.x;
    const int wid = tid >> 5;
    const int lane = tid & 31;
    const int row0 = blockIdx.y * 128;
    const int col0 = blockIdx.x * 256;
    const int kb = 0;
    const int wm0 = (wid >> 2) * 64;
    const int wn0 = (wid & 3) * 64;

    float acc[4][8][4];
    #pragma unroll
    for (int i = 0; i < 4; i++)
        #pragma unroll
        for (int j = 0; j < 8; j++)
            #pragma unroll
            for (int r = 0; r < 4; r++) acc[i][j][r] = 0.f;

    const int KT = K / 64;
    GEMM_MAINLOOP(Ah, Al, Bh, row0, col0, K, kb, KT);

    __syncthreads();
    float* tile = (float*)smc;
    #pragma unroll
    for (int mi = 0; mi < 4; mi++) {
        #pragma unroll
        for (int nj = 0; nj < 8; nj++) {
            const int r = wm0 + mi * 16 + (lane >> 2);
            const int c = wn0 + nj * 8 + (lane & 3) * 2;
            *(float2*)&tile[r * 256 + c]       = make_float2(acc[mi][nj][0], acc[mi][nj][1]);
            *(float2*)&tile[(r + 8) * 256 + c] = make_float2(acc[mi][nj][2], acc[mi][nj][3]);
        }
    }
    __syncthreads();

    #pragma unroll 4
    for (int i = 0; i < 32; i++) {
        const int idx = tid + i * 256;
        const int r = idx >> 6;
        const int rest = idx & 63;
        const int head2 = rest >> 5;
        const int d = (rest & 31) * 2;
        const int tok = row0 + r;
        const int s = tok & (SS - 1);
        const int cbase = head2 * 128;
        float x0 = tile[r * 256 + cbase + d];
        float x1 = tile[r * 256 + cbase + d + 1];
        float y0 = tile[r * 256 + cbase + d + 64];
        float y1 = tile[r * 256 + cbase + d + 65];
        const float* cp = cosT + s * HD;
        const float* sp = sinT + s * HD;
        float r0 = x0 * cp[d]      - y0 * sp[d];
        float r1 = x1 * cp[d + 1]  - y1 * sp[d + 1];
        float r2 = y0 * cp[d + 64] + x0 * sp[d + 64];
        float r3 = y1 * cp[d + 65] + x1 * sp[d + 65];
        const int gcol = col0 + cbase;
        const int g = gcol >> 7;
        size_t o = (size_t)tok * KDIM + g * HD + d;
        __half hp[2]  = {__float2half_rn(r0), __float2half_rn(r1)};
        __half hp2[2] = {__float2half_rn(r2), __float2half_rn(r3)};
        *(uint32_t*)(Kout + o)      = *(uint32_t*)hp;
        *(uint32_t*)(Kout + o + 64) = *(uint32_t*)hp2;
    }
}

// V-projection GEMM with fused transpose epilogue -> Vt fp16 (nz=1 only)
#define VT_PAD 132
__global__ __launch_bounds__(256, 1) void gemm_v_t(
    const __half* __restrict__ Ah, const __half* __restrict__ Al,
    const __half* __restrict__ Bh,
    __half* __restrict__ Vt, int M, int N, int K)
{
    extern __shared__ char smc[];
    const uint32_t sb = smem_u32(smc);
    const int tid = threadIdx.x;
    const int wid = tid >> 5;
    const int lane = tid & 31;
    const int row0 = blockIdx.y * 128;
    const int col0 = blockIdx.x * 256;
    const int kb = 0;
    const int wm0 = (wid >> 2) * 64;
    const int wn0 = (wid & 3) * 64;

    float acc[4][8][4];
    #pragma unroll
    for (int i = 0; i < 4; i++)
        #pragma unroll
        for (int j = 0; j < 8; j++)
            #pragma unroll
            for (int r = 0; r < 4; r++) acc[i][j][r] = 0.f;

    const int KT = K / 64;
    GEMM_MAINLOOP(Ah, Al, Bh, row0, col0, K, kb, KT);

    __syncthreads();
    __half* ht = (__half*)smc;
    #pragma unroll
    for (int mi = 0; mi < 4; mi++) {
        #pragma unroll
        for (int nj = 0; nj < 8; nj++) {
            const int r = wm0 + mi * 16 + (lane >> 2);
            const int c = wn0 + nj * 8 + (lane & 3) * 2;
            ht[c * VT_PAD + r]           = __float2half_rn(acc[mi][nj][0]);
            ht[(c + 1) * VT_PAD + r]     = __float2half_rn(acc[mi][nj][1]);
            ht[c * VT_PAD + r + 8]       = __float2half_rn(acc[mi][nj][2]);
            ht[(c + 1) * VT_PAD + r + 8] = __float2half_rn(acc[mi][nj][3]);
        }
    }
    __syncthreads();

    const int gcol = col0 + tid;
    const int g = gcol >> 7;
    const int d = gcol & 127;
    const int b = row0 >> 11;
    const int sbase = row0 & (SS - 1);
    __half* dst = Vt + ((size_t)((b * NKV + g) * HD) + d) * SS + sbase;
    const __half* srcc = ht + tid * VT_PAD;
    #pragma unroll 8
    for (int i = 0; i < 32; i++)
        *(uint2*)(dst + i * 4) = *(const uint2*)(srcc + i * 4);
}

// =============== fp32 -> fp16 hi/lo split (row-major) ===========
__global__ void split_rows_h(const float* __restrict__ X,
                             __half* __restrict__ Xh,
                             __half* __restrict__ Xl, int total4)
{
    int i = blockIdx.x * blockDim.x + threadIdx.x;
    if (i >= total4) return;
    float4 v = *(const float4*)(X + (size_t)i * 4);
    __half h[4], l[4];
    float vv[4] = {v.x, v.y, v.z, v.w};
    #pragma unroll
    for (int j = 0; j < 4; j++) {
        h[j] = __float2half_rn(vv[j]);
        l[j] = __float2half_rn(vv[j] - __half2float(h[j]));
    }
    *(uint2*)(Xh + (size_t)i * 4) = *(uint2*)h;
    *(uint2*)(Xl + (size_t)i * 4) = *(uint2*)l;
}

// =============== transpose + fp16 quantize: W[K,N] fp32 -> T [N,K] fp16 =====
__global__ __launch_bounds__(256) void transpose_h(
    const float* __restrict__ W, __half* __restrict__ Th, int Kd, int Nd)
{
    __shared__ float t[64][65];
    const int n0 = blockIdx.x * 64, k0 = blockIdx.y * 64;
    const int tid = threadIdx.x;
    #pragma unroll
    for (int i = 0; i < 4; i++) {
        int it = tid + i * 256;
        int r = it >> 4;
        int c4 = (it & 15) * 4;
        float4 v = *(const float4*)(W + (size_t)(k0 + r) * Nd + n0 + c4);
        t[r][c4] = v.x; t[r][c4 + 1] = v.y; t[r][c4 + 2] = v.z; t[r][c4 + 3] = v.w;
    }
    __syncthreads();
    #pragma unroll
    for (int i = 0; i < 4; i++) {
        int it = tid + i * 256;
        int n = it >> 4;
        int kc = (it & 15) * 4;
        __half h[4];
        #pragma unroll
        for (int j = 0; j < 4; j++) h[j] = __float2half_rn(t[kc + j][n]);
        *(uint2*)(Th + (size_t)(n0 + n) * Kd + k0 + kc) = *(uint2*)h;
    }
}

// =============== RoPE + fp16 hi/lo split (Q), summing two split-K buffers ===
__global__ void rope_q_h(const float* __restrict__ Q0,
                         const float* __restrict__ cosT,
                         const float* __restrict__ sinT,
                         __half* __restrict__ Xh,
                         __half* __restrict__ Xl)
{
    int idx = blockIdx.x * blockDim.x + threadIdx.x;
    int total = NT * NH * 32;
    if (idx >= total) return;
    int j = idx & 31;
    int hh = (idx >> 5) % NH;
    int t = idx / (32 * NH);
    int s = t & (SS - 1);
    int d = 2 * j;

    const float* p0 = Q0 + (size_t)t * QDIM + hh * HD;
    const float* p1 = p0 + (size_t)NT * QDIM;
    float x0 = p0[d]      + p1[d];
    float x1 = p0[d + 1]  + p1[d + 1];
    float y0 = p0[d + 64] + p1[d + 64];
    float y1 = p0[d + 65] + p1[d + 65];
    const float* cp = cosT + s * HD;
    const float* sp = sinT + s * HD;
    float r0 = x0 * cp[d]      - y0 * sp[d];
    float r1 = x1 * cp[d + 1]  - y1 * sp[d + 1];
    float r2 = y0 * cp[d + 64] + x0 * sp[d + 64];
    float r3 = y1 * cp[d + 65] + x1 * sp[d + 65];

    size_t o0 = (size_t)t * QDIM + hh * HD + d;
    __half h0 = __float2half_rn(r0), h1 = __float2half_rn(r1);
    __half h2 = __float2half_rn(r2), h3 = __float2half_rn(r3);
    __half q0 = __float2half_rn(r0 - __half2float(h0));
    __half q1 = __float2half_rn(r1 - __half2float(h1));
    __half q2 = __float2half_rn(r2 - __half2float(h2));
    __half q3 = __float2half_rn(r3 - __half2float(h3));
    __half hp[2] = {h0, h1};  *(uint32_t*)(Xh + o0) = *(uint32_t*)hp;
    __half lp[2] = {q0, q1};  *(uint32_t*)(Xl + o0) = *(uint32_t*)lp;
    __half hp2[2] = {h2, h3}; *(uint32_t*)(Xh + o0 + 64) = *(uint32_t*)hp2;
    __half lp2[2] = {q2, q3}; *(uint32_t*)(Xl + o0 + 64) = *(uint32_t*)lp2;
}

// ---------------- fp16 2-term flash attention (causal, GQA, 2-stage KV) -----
// smem: Qh 32KB | Ql 32KB | 2 stages x (K 16KB + Vt 16KB) = 128KB
#define ASMEM_BYTES (131072)

__device__ __forceinline__ void attn_load_kv(
    uint32_t st, const __half* Kh, const __half* Vt,
    int b, int g, int kt, int tid)
{
    const int tk0 = b * SS + kt * 64;
    const size_t vrow0 = (size_t)((b * NKV + g) * HD) * SS;
    #pragma unroll 8
    for (int c = tid; c < 2048; c += 256) {
        if (c < 1024) {
            int r = c >> 4, sg = c & 15, half = sg >> 3, sgi = sg & 7;
            const void* src = Kh + (size_t)(tk0 + r) * KDIM + g * HD + half * 64 + sgi * 8;
            uint32_t dst = st + half * 8192 + sw128(r * 128 + sgi * 16);
            cp_async16(dst, src);
        } else {
            int idx = c - 1024;
            int d = idx >> 3, sg = idx & 7;
            const void* src = Vt + vrow0 + (size_t)d * SS + kt * 64 + sg * 8;
            uint32_t dst = st + 16384 + sw128(d * 128 + sg * 16);
            cp_async16(dst, src);
        }
    }
    CP_COMMIT();
}

__global__ __launch_bounds__(256, 1) void attn_mma(
    const __half* __restrict__ Qh, const __half* __restrict__ Ql,
    const __half* __restrict__ Kh, const __half* __restrict__ Vt,
    __half* __restrict__ Oh)
{
    extern __shared__ char smc[];
    const uint32_t sb = smem_u32(smc);
    const int tid = threadIdx.x, wid = tid >> 5, lane = tid & 31;
    const int bid = blockIdx.x;
    const int qb = 15 - (bid >> 6);     // heavy-first
    const int bh = bid & 63;
    const int b = bh >> 5, h = bh & 31, g = h >> 2;
    const int tok0 = b * SS + qb * 128;
    const int KT = 2 * qb + 2;
    const float SCL = 0.08838834764831845f * 1.4426950408889634f;

    #pragma unroll 4
    for (int c = tid; c < 4096; c += 256) {
        int hl = c >> 11, cc = c & 2047;
        int r = cc >> 4, sg = cc & 15, half = sg >> 3, sgi = sg & 7;
        const __half* base = hl ? Ql : Qh;
        const void* src = base + (size_t)(tok0 + r) * QDIM + h * HD + half * 64 + sgi * 8;
        uint32_t dst = sb + hl * 32768 + half * 16384 + sw128(r * 128 + sgi * 16);
        cp_async16(dst, src);
    }
    attn_load_kv(sb + 65536, Kh, Vt, b, g, 0, tid);

    float o[16][4];
    #pragma unroll
    for (int nd = 0; nd < 16; nd++)
        #pragma unroll
        for (int e = 0; e < 4; e++) o[nd][e] = 0.f;
    float m0 = -1e30f, m1 = -1e30f, l0 = 0.f, l1 = 0.f;

    const int qg0 = qb * 128 + wid * 16 + (lane >> 2);
    const int qg1 = qg0 + 8;

    for (int kt = 0; kt < KT; kt++) {
        CP_WAIT0();
        __syncthreads();
        if (kt + 1 < KT)
            attn_load_kv(sb + 65536 + ((kt + 1) & 1) * 32768, Kh, Vt, b, g, kt + 1, tid);

        const uint32_t st = sb + 65536 + (kt & 1) * 32768;
        const bool skip = kt * 64 > qb * 128 + wid * 16 + 15;

        if (!skip) {
            float s[8][4];
            #pragma unroll
            for (int nj = 0; nj < 8; nj++)
                #pragma unroll
                for (int e = 0; e < 4; e++) s[nj][e] = 0.f;

            #pragma unroll
            for (int k16 = 0; k16 < 8; k16++) {
                const int half = k16 >> 2;
                const int cb = (k16 & 3) * 32 + (lane >> 4) * 16;
                const uint32_t qoff = sw128((wid * 16 + (lane & 15)) * 128 + cb);
                uint32_t ah[4], al[4];
                LDSM4(ah, sb + half * 16384 + qoff);
                LDSM4(al, sb + 32768 + half * 16384 + qoff);
                uint32_t bhf[4][4];
                #pragma unroll
                for (int c = 0; c < 4; c++) {
                    const uint32_t koff = sw128((c * 16 + (lane & 15)) * 128 + cb);
                    LDSM4(bhf[c], st + half * 8192 + koff);
                }
                #pragma unroll
                for (int nj = 0; nj < 8; nj++) {
                    const int np = nj >> 1, h2 = nj & 1;
                    MMAH16816(s[nj], ah, bhf[np][h2], bhf[np][2 + h2]);
                }
                #pragma unroll
                for (int nj = 0; nj < 8; nj++) {
                    const int np = nj >> 1, h2 = nj & 1;
                    MMAH16816(s[nj], al, bhf[np][h2], bhf[np][2 + h2]);
                }
            }

            const bool domask = (kt * 64 + 63) > qg0;
            #pragma unroll
            for (int nj = 0; nj < 8; nj++) {
                #pragma unroll
                for (int e = 0; e < 4; e++) s[nj][e] *= SCL;
                if (domask) {
                    const int kc = kt * 64 + nj * 8 + (lane & 3) * 2;
                    if (kc     > qg0) s[nj][0] = -1e30f;
                    if (kc + 1 > qg0) s[nj][1] = -1e30f;
                    if (kc     > qg1) s[nj][2] = -1e30f;
                    if (kc + 1 > qg1) s[nj][3] = -1e30f;
                }
            }
            float mx0 = -1e30f, mx1 = -1e30f;
            #pragma unroll
            for (int nj = 0; nj < 8; nj++) {
                mx0 = fmaxf(mx0, fmaxf(s[nj][0], s[nj][1]));
                mx1 = fmaxf(mx1, fmaxf(s[nj][2], s[nj][3]));
            }
            mx0 = fmaxf(mx0, __shfl_xor_sync(0xffffffffu, mx0, 1));
            mx0 = fmaxf(mx0, __shfl_xor_sync(0xffffffffu, mx0, 2));
            mx1 = fmaxf(mx1, __shfl_xor_sync(0xffffffffu, mx1, 1));
            mx1 = fmaxf(mx1, __shfl_xor_sync(0xffffffffu, mx1, 2));
            const float nm0 = fmaxf(m0, mx0), nm1 = fmaxf(m1, mx1);
            const float c0 = exp2a(m0 - nm0), c1 = exp2a(m1 - nm1);
            float rs0 = 0.f, rs1 = 0.f;
            #pragma unroll
            for (int nj = 0; nj < 8; nj++) {
                s[nj][0] = exp2a(s[nj][0] - nm0);
                s[nj][1] = exp2a(s[nj][1] - nm0);
                s[nj][2] = exp2a(s[nj][2] - nm1);
                s[nj][3] = exp2a(s[nj][3] - nm1);
                rs0 += s[nj][0] + s[nj][1];
                rs1 += s[nj][2] + s[nj][3];
            }
            rs0 += __shfl_xor_sync(0xffffffffu, rs0, 1);
            rs0 += __shfl_xor_sync(0xffffffffu, rs0, 2);
            rs1 += __shfl_xor_sync(0xffffffffu, rs1, 1);
            rs1 += __shfl_xor_sync(0xffffffffu, rs1, 2);
            m0 = nm0; m1 = nm1;
            l0 = l0 * c0 + rs0;
            l1 = l1 * c1 + rs1;
            #pragma unroll
            for (int nd = 0; nd < 16; nd++) {
                o[nd][0] *= c0; o[nd][1] *= c0;
                o[nd][2] *= c1; o[nd][3] *= c1;
            }

            #pragma unroll
            for (int j2 = 0; j2 < 4; j2++) {
                const int n0 = 2 * j2, n1 = 2 * j2 + 1;
                uint32_t aPh[4], aPl[4];
                __half2 t0 = __floats2half2_rn(s[n0][0], s[n0][1]);
                __half2 t1 = __floats2half2_rn(s[n0][2], s[n0][3]);
                __half2 t2 = __floats2half2_rn(s[n1][0], s[n1][1]);
                __half2 t3 = __floats2half2_rn(s[n1][2], s[n1][3]);
                aPh[0] = *(uint32_t*)&t0; aPh[1] = *(uint32_t*)&t1;
                aPh[2] = *(uint32_t*)&t2; aPh[3] = *(uint32_t*)&t3;
                __half2 u0 = __floats2half2_rn(s[n0][0] - __low2float(t0),
                                               s[n0][1] - __high2float(t0));
                __half2 u1 = __floats2half2_rn(s[n0][2] - __low2float(t1),
                                               s[n0][3] - __high2float(t1));
                __half2 u2 = __floats2half2_rn(s[n1][0] - __low2float(t2),
                                               s[n1][1] - __high2float(t2));
                __half2 u3 = __floats2half2_rn(s[n1][2] - __low2float(t3),
                                               s[n1][3] - __high2float(t3));
                aPl[0] = *(uint32_t*)&u0; aPl[1] = *(uint32_t*)&u1;
                aPl[2] = *(uint32_t*)&u2; aPl[3] = *(uint32_t*)&u3;

                #pragma unroll
                for (int c = 0; c < 8; c++) {
                    const uint32_t voff = sw128((c * 16 + (lane & 15)) * 128 + j2 * 32 + (lane >> 4) * 16);
                    uint32_t vh[4];
                    LDSM4(vh, st + 16384 + voff);
                    MMAH16816(o[2 * c],     aPh, vh[0], vh[2]);
                    MMAH16816(o[2 * c + 1], aPh, vh[1], vh[3]);
                    MMAH16816(o[2 * c],     aPl, vh[0], vh[2]);
                    MMAH16816(o[2 * c + 1], aPl, vh[1], vh[3]);
                }
            }
        }
    }

    // epilogue: normalize, single fp16 output (Wo GEMM is 1-term)
    const float il0 = 1.f / l0, il1 = 1.f / l1;
    const int row0g = tok0 + wid * 16 + (lane >> 2);
    #pragma unroll
    for (int nd = 0; nd < 16; nd++) {
        const int col = h * HD + nd * 8 + (lane & 3) * 2;
        __half2 h0 = __floats2half2_rn(o[nd][0] * il0, o[nd][1] * il0);
        __half2 h1 = __floats2half2_rn(o[nd][2] * il1, o[nd][3] * il1);
        *(uint32_t*)(Oh + (size_t)row0g * QDIM + col)       = *(uint32_t*)&h0;
        *(uint32_t*)(Oh + (size_t)(row0g + 8) * QDIM + col) = *(uint32_t*)&h1;
    }
}

// ---------------- launcher ---------------------------------------------------
extern "C" void kernel_launch(void* const* d_in, const int* in_sizes, int n_in,
                              void* d_out, int out_size)
{
    const float* x    = (const float*)d_in[0];
    const float* cosT = (const float*)d_in[1];
    const float* sinT = (const float*)d_in[2];
    const float* Wq   = (const float*)d_in[3];
    const float* Wk   = (const float*)d_in[4];
    const float* Wv   = (const float*)d_in[5];
    const float* Wo   = (const float*)d_in[6];
    float* out = (float*)d_out;

    float* Q;
    __half *xh, *xl, *Wqh, *Wkh, *Wvh, *Woh, *Ah;
    __half *Qah, *Qal, *Kah, *Vt;
    cudaGetSymbolAddress((void**)&Q, g_Q);
    cudaGetSymbolAddress((void**)&xh, g_xh);
    cudaGetSymbolAddress((void**)&xl, g_xl);
    cudaGetSymbolAddress((void**)&Wqh, g_Wqh);
    cudaGetSymbolAddress((void**)&Wkh, g_Wkh);
    cudaGetSymbolAddress((void**)&Wvh, g_Wvh);
    cudaGetSymbolAddress((void**)&Woh, g_Woh);
    cudaGetSymbolAddress((void**)&Ah, g_Ah);
    cudaGetSymbolAddress((void**)&Qah, g_Qah);
    cudaGetSymbolAddress((void**)&Qal, g_Qal);
    cudaGetSymbolAddress((void**)&Kah, g_Kah);
    cudaGetSymbolAddress((void**)&Vt, g_Vt);

    cudaFuncSetAttribute(gemm_fp16x2, cudaFuncAttributeMaxDynamicSharedMemorySize, GSMEM_BYTES);
    cudaFuncSetAttribute(gemm_fp16x1_atomic, cudaFuncAttributeMaxDynamicSharedMemorySize, GSMEM1_BYTES);
    cudaFuncSetAttribute(gemm_k_rope, cudaFuncAttributeMaxDynamicSharedMemorySize, GSMEM_BYTES);
    cudaFuncSetAttribute(gemm_v_t, cudaFuncAttributeMaxDynamicSharedMemorySize, GSMEM_BYTES);
    cudaFuncSetAttribute(attn_mma, cudaFuncAttributeMaxDynamicSharedMemorySize, ASMEM_BYTES);

    // zero-init only the Wo split-K target
    cudaMemsetAsync(out, 0, (size_t)NT * DIM * sizeof(float));

    // conversions
    split_rows_h<<<(NT * DIM / 4 + 255) / 256, 256>>>(x, xh, xl, NT * DIM / 4);
    transpose_h<<<dim3(QDIM / 64, DIM / 64), 256>>>(Wq, Wqh, DIM, QDIM);
    transpose_h<<<dim3(KDIM / 64, DIM / 64), 256>>>(Wk, Wkh, DIM, KDIM);
    transpose_h<<<dim3(KDIM / 64, DIM / 64), 256>>>(Wv, Wvh, DIM, KDIM);
    transpose_h<<<dim3(DIM / 64, QDIM / 64), 256>>>(Wo, Woh, QDIM, DIM);

    // Q projection: split-K=2 into two plain-store buffers (no memset/atomics)
    gemm_fp16x2<<<dim3(QDIM / 256, NT / 128, 2), 256, GSMEM_BYTES>>>(xh, xl, Wqh, Q, NT, QDIM, DIM, 1);
    // K projection with fused RoPE -> Kah
    gemm_k_rope<<<dim3(KDIM / 256, NT / 128, 1), 256, GSMEM_BYTES>>>(xh, xl, Wkh, cosT, sinT, Kah, NT, KDIM, DIM);
    // V projection with fused transpose -> Vt
    gemm_v_t<<<dim3(KDIM / 256, NT / 128, 1), 256, GSMEM_BYTES>>>(xh, xl, Wvh, Vt, NT, KDIM, DIM);

    // Q: sum split buffers + RoPE + fp16 split
    rope_q_h<<<(NT * NH * 32 + 255) / 256, 256>>>(Q, cosT, sinT, Qah, Qal);

    // fp16 2-term flash attention -> single fp16 output
    attn_mma<<<1024, 256, ASMEM_BYTES>>>(Qah, Qal, Kah, Vt, Ah);

    // Output projection (fp16 1-term, split-K=2, atomic into zeroed out)
    gemm_fp16x1_atomic<<<dim3(DIM / 256, NT / 128, 2), 256, GSMEM1_BYTES>>>(Ah, Woh, out, NT, DIM, QDIM);
}

// round 16
// speedup vs baseline: 1.4120x; 1.1759x over previous
#include <cuda_runtime.h>
#include <cuda_bf16.h>
#include <cuda_fp16.h>
#include <math.h>
#include <stdint.h>

// Problem constants
#define BB   2
#define SS   2048
#define DIM  4096
#define NH   32
#define NKV  8
#define HD   128
#define NT   (BB*SS)          // 4096 tokens
#define QDIM (NH*HD)          // 4096
#define KDIM (NKV*HD)         // 1024

// ---------------- scratch (device globals; no allocation allowed) ----------
__device__ float g_Q[2 * NT * QDIM];     // two split-K partial buffers
__device__ __half g_xh[NT * DIM];
__device__ __half g_xl[NT * DIM];
__device__ __half g_Wqh[QDIM * DIM];     // transposed [N][K]
__device__ __half g_Wkh[KDIM * DIM];
__device__ __half g_Wvh[KDIM * DIM];
__device__ __half g_Woh[DIM * QDIM];
__device__ __half g_Ah[NT * QDIM];       // attention out (fp16, single)
__device__ __half g_Qah[NT * QDIM];      // Q hi (exact split)
__device__ __half g_Qal[NT * QDIM];      // Q lo
__device__ __half g_Kah[NT * KDIM];      // K single fp16 (RoPE'd)
__device__ __half g_Vt[BB * NKV * HD * SS];  // V transposed [b][g][d][s]

// ======================= PTX helpers =======================
__device__ __forceinline__ uint32_t smem_u32(const void* p) {
    uint32_t a;
    asm("{ .reg .u64 t; cvta.to.shared.u64 t, %1; cvt.u32.u64 %0, t; }" : "=r"(a) : "l"(p));
    return a;
}
__device__ __forceinline__ void cp_async16(uint32_t dst, const void* src) {
    asm volatile("cp.async.cg.shared.global [%0], [%1], 16;" :: "r"(dst), "l"(src));
}
#define CP_COMMIT() asm volatile("cp.async.commit_group;" ::: "memory")
#define CP_WAIT0()  asm volatile("cp.async.wait_group 0;" ::: "memory")

__device__ __forceinline__ uint32_t sw128(uint32_t b) { return b ^ ((b >> 3) & 0x70); }

__device__ __forceinline__ float exp2a(float x) {
    float r;
    asm("ex2.approx.f32 %0, %1;" : "=f"(r) : "f"(x));
    return r;
}

#define LDSM4(r, addr) \
    asm volatile("ldmatrix.sync.aligned.m8n8.x4.shared.b16 {%0,%1,%2,%3}, [%4];" \
        : "=r"((r)[0]), "=r"((r)[1]), "=r"((r)[2]), "=r"((r)[3]) : "r"(addr))

#define MMAH16816(c, a, b0, b1) \
    asm volatile("mma.sync.aligned.m16n8k16.row.col.f32.f16.f16.f32 " \
        "{%0,%1,%2,%3}, {%4,%5,%6,%7}, {%8,%9}, {%0,%1,%2,%3};" \
        : "+f"((c)[0]), "+f"((c)[1]), "+f"((c)[2]), "+f"((c)[3]) \
        : "r"((a)[0]), "r"((a)[1]), "r"((a)[2]), "r"((a)[3]), "r"(b0), "r"(b1))

// =============== fp16 2-term HMMA GEMM core (2-stage, 128x256 tile) =========
#define GSMEM_BYTES (2 * 65536)

__device__ __forceinline__ void load_stage_part(
    uint32_t buf, const __half* Ah, const __half* Al, const __half* Bh,
    int row0, int col0, int K, int kchunk, int tid, int part)
{
    #pragma unroll
    for (int j = 0; j < 4; j++) {
        const int c = tid + part * 1024 + j * 256;
        if (c < 1024) {
            const int r = c >> 3, sg = c & 7;
            const uint32_t dst = buf + sw128(r * 128 + sg * 16);
            cp_async16(dst, Ah + (size_t)(row0 + r) * K + kchunk * 64 + sg * 8);
        } else if (c < 2048) {
            const int idx = c - 1024;
            const int r = idx >> 3, sg = idx & 7;
            const uint32_t dst = buf + 16384 + sw128(r * 128 + sg * 16);
            cp_async16(dst, Al + (size_t)(row0 + r) * K + kchunk * 64 + sg * 8);
        } else {
            const int idx = c - 2048;
            const int r = idx >> 3, sg = idx & 7;      // r 0..255
            const uint32_t dst = buf + 32768 + sw128(r * 128 + sg * 16);
            cp_async16(dst, Bh + (size_t)(col0 + r) * K + kchunk * 64 + sg * 8);
        }
    }
}

// 2-term mainloop; results in acc[4][8][4].
// single-group-ahead pipeline -> wait at loop head MUST be wait_group 0.
#define GEMM_MAINLOOP(Ah, Al, Bh, row0, col0, K, kb, KT)                        \
    {                                                                           \
        _Pragma("unroll")                                                       \
        for (int p = 0; p < 4; p++)                                             \
            load_stage_part(sb, Ah, Al, Bh, row0, col0, K, kb, tid, p);         \
        CP_COMMIT();                                                            \
        for (int it = 0; it < KT; it++) {                                       \
            const uint32_t buf = sb + (it & 1) * 65536;                         \
            const uint32_t nbuf = sb + ((it + 1) & 1) * 65536;                  \
            const bool more = (it + 1 < KT);                                    \
            CP_WAIT0();                                                         \
            __syncthreads();                                                    \
            const uint32_t aHb = buf;                                           \
            const uint32_t aLb = buf + 16384;                                   \
            const uint32_t bHb = buf + 32768;                                   \
            _Pragma("unroll")                                                   \
            for (int k16 = 0; k16 < 4; k16++) {                                 \
                if (more) {                                                     \
                    load_stage_part(nbuf, Ah, Al, Bh, row0, col0, K, kb + it + 1, tid, k16); \
                    if (k16 == 3) CP_COMMIT();                                  \
                }                                                               \
                const int colb = k16 * 32 + (lane >> 4) * 16;                   \
                uint32_t ahf[4][4], alf[4][4];                                  \
                _Pragma("unroll")                                               \
                for (int mi = 0; mi < 4; mi++) {                                \
                    const uint32_t off = sw128((wm0 + mi * 16 + (lane & 15)) * 128 + colb); \
                    LDSM4(ahf[mi], aHb + off);                                  \
                    LDSM4(alf[mi], aLb + off);                                  \
                }                                                               \
                _Pragma("unroll")                                               \
                for (int hb = 0; hb < 2; hb++) {                                \
                    uint32_t bh[2][4];                                          \
                    _Pragma("unroll")                                           \
                    for (int np = 0; np < 2; np++) {                            \
                        const uint32_t off =                                    \
                            sw128((wn0 + hb * 32 + np * 16 + (lane & 15)) * 128 + colb); \
                        LDSM4(bh[np], bHb + off);                               \
                    }                                                           \
                    _Pragma("unroll")                                           \
                    for (int mi = 0; mi < 4; mi++)                              \
                        _Pragma("unroll")                                       \
                        for (int nj = 0; nj < 4; nj++) {                        \
                            const int np = nj >> 1, hq = nj & 1;                \
                            MMAH16816(acc[mi][hb * 4 + nj], ahf[mi], bh[np][hq], bh[np][2 + hq]); \
                        }                                                       \
                    _Pragma("unroll")                                           \
                    for (int mi = 0; mi < 4; mi++)                              \
                        _Pragma("unroll")                                       \
                        for (int nj = 0; nj < 4; nj++) {                        \
                            const int np = nj >> 1, hq = nj & 1;                \
                            MMAH16816(acc[mi][hb * 4 + nj], alf[mi], bh[np][hq], bh[np][2 + hq]); \
                        }                                                       \
                }                                                               \
            }                                                                   \
        }                                                                       \
    }

// ---- 1-term variant (A single): stage = Ah 16KB | Bh 32KB = 48KB ----
#define GSMEM1_STAGE 49152
#define GSMEM1_BYTES (2 * GSMEM1_STAGE)

__device__ __forceinline__ void load_stage_part_1t(
    uint32_t buf, const __half* Ah, const __half* Bh,
    int row0, int col0, int K, int kchunk, int tid, int part)
{
    #pragma unroll
    for (int j = 0; j < 3; j++) {
        const int c = tid + part * 768 + j * 256;
        if (c < 1024) {
            const int r = c >> 3, sg = c & 7;
            const uint32_t dst = buf + sw128(r * 128 + sg * 16);
            cp_async16(dst, Ah + (size_t)(row0 + r) * K + kchunk * 64 + sg * 8);
        } else {
            const int idx = c - 1024;
            const int r = idx >> 3, sg = idx & 7;      // r 0..255
            const uint32_t dst = buf + 16384 + sw128(r * 128 + sg * 16);
            cp_async16(dst, Bh + (size_t)(col0 + r) * K + kchunk * 64 + sg * 8);
        }
    }
}

#define GEMM_MAINLOOP_1T(Ah, Bh, row0, col0, K, kb, KT)                         \
    {                                                                           \
        _Pragma("unroll")                                                       \
        for (int p = 0; p < 4; p++)                                             \
            load_stage_part_1t(sb, Ah, Bh, row0, col0, K, kb, tid, p);          \
        CP_COMMIT();                                                            \
        for (int it = 0; it < KT; it++) {                                       \
            const uint32_t buf = sb + (it & 1) * GSMEM1_STAGE;                  \
            const uint32_t nbuf = sb + ((it + 1) & 1) * GSMEM1_STAGE;           \
            const bool more = (it + 1 < KT);                                    \
            CP_WAIT0();                                                         \
            __syncthreads();                                                    \
            const uint32_t aHb = buf;                                           \
            const uint32_t bHb = buf + 16384;                                   \
            _Pragma("unroll")                                                   \
            for (int k16 = 0; k16 < 4; k16++) {                                 \
                if (more) {                                                     \
                    load_stage_part_1t(nbuf, Ah, Bh, row0, col0, K, kb + it + 1, tid, k16); \
                    if (k16 == 3) CP_COMMIT();                                  \
                }                                                               \
                const int colb = k16 * 32 + (lane >> 4) * 16;                   \
                uint32_t ahf[4][4];                                             \
                _Pragma("unroll")                                               \
                for (int mi = 0; mi < 4; mi++) {                                \
                    const uint32_t off = sw128((wm0 + mi * 16 + (lane & 15)) * 128 + colb); \
                    LDSM4(ahf[mi], aHb + off);                                  \
                }                                                               \
                _Pragma("unroll")                                               \
                for (int hb = 0; hb < 2; hb++) {                                \
                    uint32_t bh[2][4];                                          \
                    _Pragma("unroll")                                           \
                    for (int np = 0; np < 2; np++) {                            \
                        const uint32_t off =                                    \
                            sw128((wn0 + hb * 32 + np * 16 + (lane & 15)) * 128 + colb); \
                        LDSM4(bh[np], bHb + off);                               \
                    }                                                           \
                    _Pragma("unroll")                                           \
                    for (int mi = 0; mi < 4; mi++)                              \
                        _Pragma("unroll")                                       \
                        for (int nj = 0; nj < 4; nj++) {                        \
                            const int np = nj >> 1, hq = nj & 1;                \
                            MMAH16816(acc[mi][hb * 4 + nj], ahf[mi], bh[np][hq], bh[np][2 + hq]); \
                        }                                                       \
                }                                                               \
            }                                                                   \
        }                                                                       \
    }

// 2-term GEMM: mode 0 = plain store; mode 1 = store to C + z*M*N
__global__ __launch_bounds__(256, 1) void gemm_fp16x2(
    const __half* __restrict__ Ah, const __half* __restrict__ Al,
    const __half* __restrict__ Bh,
    float* __restrict__ C, int M, int N, int K, int mode)
{
    extern __shared__ char smc[];
    const uint32_t sb = smem_u32(smc);
    const int tid = threadIdx.x;
    const int wid = tid >> 5;
    const int lane = tid & 31;
    const int row0 = blockIdx.y * 128;
    const int col0 = blockIdx.x * 256;
    const int nz = gridDim.z;
    const int K2 = K / nz;
    const int kb = blockIdx.z * (K2 / 64);
    const int wm0 = (wid >> 2) * 64;
    const int wn0 = (wid & 3) * 64;

    float acc[4][8][4];
    #pragma unroll
    for (int i = 0; i < 4; i++)
        #pragma unroll
        for (int j = 0; j < 8; j++)
            #pragma unroll
            for (int r = 0; r < 4; r++) acc[i][j][r] = 0.f;

    const int KT = K2 / 64;
    GEMM_MAINLOOP(Ah, Al, Bh, row0, col0, K, kb, KT);

    float* Cz = (mode == 1) ? (C + (size_t)blockIdx.z * M * N) : C;
    #pragma unroll
    for (int mi = 0; mi < 4; mi++) {
        #pragma unroll
        for (int nj = 0; nj < 8; nj++) {
            const int row = row0 + wm0 + mi * 16 + (lane >> 2);
            const int col = col0 + wn0 + nj * 8 + (lane & 3) * 2;
            *(float2*)(Cz + (size_t)row * N + col)       = make_float2(acc[mi][nj][0], acc[mi][nj][1]);
            *(float2*)(Cz + (size_t)(row + 8) * N + col) = make_float2(acc[mi][nj][2], acc[mi][nj][3]);
        }
    }
}

// 1-term GEMM: mode 0 = plain store; mode 1 = store to C + z*M*N (Q split-K)
__global__ __launch_bounds__(256, 1) void gemm_fp16x1(
    const __half* __restrict__ Ah, const __half* __restrict__ Bh,
    float* __restrict__ C, int M, int N, int K, int mode)
{
    extern __shared__ char smc[];
    const uint32_t sb = smem_u32(smc);
    const int tid = threadIdx.x;
    const int wid = tid >> 5;
    const int lane = tid & 31;
    const int row0 = blockIdx.y * 128;
    const int col0 = blockIdx.x * 256;
    const int nz = gridDim.z;
    const int K2 = K / nz;
    const int kb = blockIdx.z * (K2 / 64);
    const int wm0 = (wid >> 2) * 64;
    const int wn0 = (wid & 3) * 64;

    float acc[4][8][4];
    #pragma unroll
    for (int i = 0; i < 4; i++)
        #pragma unroll
        for (int j = 0; j < 8; j++)
            #pragma unroll
            for (int r = 0; r < 4; r++) acc[i][j][r] = 0.f;

    const int KT = K2 / 64;
    GEMM_MAINLOOP_1T(Ah, Bh, row0, col0, K, kb, KT);

    float* Cz = (mode == 1) ? (C + (size_t)blockIdx.z * M * N) : C;
    #pragma unroll
    for (int mi = 0; mi < 4; mi++) {
        #pragma unroll
        for (int nj = 0; nj < 8; nj++) {
            const int row = row0 + wm0 + mi * 16 + (lane >> 2);
            const int col = col0 + wn0 + nj * 8 + (lane & 3) * 2;
            *(float2*)(Cz + (size_t)row * N + col)       = make_float2(acc[mi][nj][0], acc[mi][nj][1]);
            *(float2*)(Cz + (size_t)(row + 8) * N + col) = make_float2(acc[mi][nj][2], acc[mi][nj][3]);
        }
    }
}

// 1-term GEMM with atomic accumulation (Wo split-K into zeroed out)
__global__ __launch_bounds__(256, 1) void gemm_fp16x1_atomic(
    const __half* __restrict__ Ah, const __half* __restrict__ Bh,
    float* __restrict__ C, int M, int N, int K)
{
    extern __shared__ char smc[];
    const uint32_t sb = smem_u32(smc);
    const int tid = threadIdx.x;
    const int wid = tid >> 5;
    const int lane = tid & 31;
    const int row0 = blockIdx.y * 128;
    const int col0 = blockIdx.x * 256;
    const int nz = gridDim.z;
    const int K2 = K / nz;
    const int kb = blockIdx.z * (K2 / 64);
    const int wm0 = (wid >> 2) * 64;
    const int wn0 = (wid & 3) * 64;

    float acc[4][8][4];
    #pragma unroll
    for (int i = 0; i < 4; i++)
        #pragma unroll
        for (int j = 0; j < 8; j++)
            #pragma unroll
            for (int r = 0; r < 4; r++) acc[i][j][r] = 0.f;

    const int KT = K2 / 64;
    GEMM_MAINLOOP_1T(Ah, Bh, row0, col0, K, kb, KT);

    #pragma unroll
    for (int mi = 0; mi < 4; mi++) {
        #pragma unroll
        for (int nj = 0; nj < 8; nj++) {
            const int row = row0 + wm0 + mi * 16 + (lane >> 2);
            const int col = col0 + wn0 + nj * 8 + (lane & 3) * 2;
            float* p0 = C + (size_t)row * N + col;
            float* p1 = C + (size_t)(row + 8) * N + col;
            atomicAdd(p0,     acc[mi][nj][0]);
            atomicAdd(p0 + 1, acc[mi][nj][1]);
            atomicAdd(p1,     acc[mi][nj][2]);
            atomicAdd(p1 + 1, acc[mi][nj][3]);
        }
    }
}

// K-projection GEMM with fused RoPE epilogue -> Kah fp16 (nz=1 only)
__global__ __launch_bounds__(256, 1) void gemm_k_rope(
    const __half* __restrict__ Ah, const __half* __restrict__ Al,
    const __half* __restrict__ Bh,
    const float* __restrict__ cosT, const float* __restrict__ sinT,
    __half* __restrict__ Kout, int M, int N, int K)
{
    extern __shared__ char smc[];
    const uint32_t sb = smem_u32(smc);
    const int tid = threadIdx.x;
    const int wid = tid >> 5;
    const int lane = tid & 31;
    const int row0 = blockIdx.y * 128;
    const int col0 = blockIdx.x * 256;
    const int kb = 0;
    const int wm0 = (wid >> 2) * 64;
    const int wn0 = (wid & 3) * 64;

    float acc[4][8][4];
    #pragma unroll
    for (int i = 0; i < 4; i++)
        #pragma unroll
        for (int j = 0; j < 8; j++)
            #pragma unroll
            for (int r = 0; r < 4; r++) acc[i][j][r] = 0.f;

    const int KT = K / 64;
    GEMM_MAINLOOP(Ah, Al, Bh, row0, col0, K, kb, KT);

    __syncthreads();
    float* tile = (float*)smc;
    #pragma unroll
    for (int mi = 0; mi < 4; mi++) {
        #pragma unroll
        for (int nj = 0; nj < 8; nj++) {
            const int r = wm0 + mi * 16 + (lane >> 2);
            const int c = wn0 + nj * 8 + (lane & 3) * 2;
            *(float2*)&tile[r * 256 + c]       = make_float2(acc[mi][nj][0], acc[mi][nj][1]);
            *(float2*)&tile[(r + 8) * 256 + c] = make_float2(acc[mi][nj][2], acc[mi][nj][3]);
        }
    }
    __syncthreads();

    #pragma unroll 4
    for (int i = 0; i < 32; i++) {
        const int idx = tid + i * 256;
        const int r = idx >> 6;
        const int rest = idx & 63;
        const int head2 = rest >> 5;
        const int d = (rest & 31) * 2;
        const int tok = row0 + r;
        const int s = tok & (SS - 1);
        const int cbase = head2 * 128;
        float x0 = tile[r * 256 + cbase + d];
        float x1 = tile[r * 256 + cbase + d + 1];
        float y0 = tile[r * 256 + cbase + d + 64];
        float y1 = tile[r * 256 + cbase + d + 65];
        const float* cp = cosT + s * HD;
        const float* sp = sinT + s * HD;
        float r0 = x0 * cp[d]      - y0 * sp[d];
        float r1 = x1 * cp[d + 1]  - y1 * sp[d + 1];
        float r2 = y0 * cp[d + 64] + x0 * sp[d + 64];
        float r3 = y1 * cp[d + 65] + x1 * sp[d + 65];
        const int gcol = col0 + cbase;
        const int g = gcol >> 7;
        size_t o = (size_t)tok * KDIM + g * HD + d;
        __half hp[2]  = {__float2half_rn(r0), __float2half_rn(r1)};
        __half hp2[2] = {__float2half_rn(r2), __float2half_rn(r3)};
        *(uint32_t*)(Kout + o)      = *(uint32_t*)hp;
        *(uint32_t*)(Kout + o + 64) = *(uint32_t*)hp2;
    }
}

// V-projection GEMM with fused transpose epilogue -> Vt fp16 (nz=1 only)
#define VT_PAD 132
__global__ __launch_bounds__(256, 1) void gemm_v_t(
    const __half* __restrict__ Ah, const __half* __restrict__ Al,
    const __half* __restrict__ Bh,
    __half* __restrict__ Vt, int M, int N, int K)
{
    extern __shared__ char smc[];
    const uint32_t sb = smem_u32(smc);
    const int tid = threadIdx.x;
    const int wid = tid >> 5;
    const int lane = tid & 31;
    const int row0 = blockIdx.y * 128;
    const int col0 = blockIdx.x * 256;
    const int kb = 0;
    const int wm0 = (wid >> 2) * 64;
    const int wn0 = (wid & 3) * 64;

    float acc[4][8][4];
    #pragma unroll
    for (int i = 0; i < 4; i++)
        #pragma unroll
        for (int j = 0; j < 8; j++)
            #pragma unroll
            for (int r = 0; r < 4; r++) acc[i][j][r] = 0.f;

    const int KT = K / 64;
    GEMM_MAINLOOP(Ah, Al, Bh, row0, col0, K, kb, KT);

    __syncthreads();
    __half* ht = (__half*)smc;
    #pragma unroll
    for (int mi = 0; mi < 4; mi++) {
        #pragma unroll
        for (int nj = 0; nj < 8; nj++) {
            const int r = wm0 + mi * 16 + (lane >> 2);
            const int c = wn0 + nj * 8 + (lane & 3) * 2;
            ht[c * VT_PAD + r]           = __float2half_rn(acc[mi][nj][0]);
            ht[(c + 1) * VT_PAD + r]     = __float2half_rn(acc[mi][nj][1]);
            ht[c * VT_PAD + r + 8]       = __float2half_rn(acc[mi][nj][2]);
            ht[(c + 1) * VT_PAD + r + 8] = __float2half_rn(acc[mi][nj][3]);
        }
    }
    __syncthreads();

    const int gcol = col0 + tid;
    const int g = gcol >> 7;
    const int d = gcol & 127;
    const int b = row0 >> 11;
    const int sbase = row0 & (SS - 1);
    __half* dst = Vt + ((size_t)((b * NKV + g) * HD) + d) * SS + sbase;
    const __half* srcc = ht + tid * VT_PAD;
    #pragma unroll 8
    for (int i = 0; i < 32; i++)
        *(uint2*)(dst + i * 4) = *(const uint2*)(srcc + i * 4);
}

// =============== fp32 -> fp16 hi/lo split (row-major) ===========
__global__ void split_rows_h(const float* __restrict__ X,
                             __half* __restrict__ Xh,
                             __half* __restrict__ Xl, int total4)
{
    int i = blockIdx.x * blockDim.x + threadIdx.x;
    if (i >= total4) return;
    float4 v = *(const float4*)(X + (size_t)i * 4);
    __half h[4], l[4];
    float vv[4] = {v.x, v.y, v.z, v.w};
    #pragma unroll
    for (int j = 0; j < 4; j++) {
        h[j] = __float2half_rn(vv[j]);
        l[j] = __float2half_rn(vv[j] - __half2float(h[j]));
    }
    *(uint2*)(Xh + (size_t)i * 4) = *(uint2*)h;
    *(uint2*)(Xl + (size_t)i * 4) = *(uint2*)l;
}

// =============== transpose + fp16 quantize: W[K,N] fp32 -> T [N,K] fp16 =====
__global__ __launch_bounds__(256) void transpose_h(
    const float* __restrict__ W, __half* __restrict__ Th, int Kd, int Nd)
{
    __shared__ float t[64][65];
    const int n0 = blockIdx.x * 64, k0 = blockIdx.y * 64;
    const int tid = threadIdx.x;
    #pragma unroll
    for (int i = 0; i < 4; i++) {
        int it = tid + i * 256;
        int r = it >> 4;
        int c4 = (it & 15) * 4;
        float4 v = *(const float4*)(W + (size_t)(k0 + r) * Nd + n0 + c4);
        t[r][c4] = v.x; t[r][c4 + 1] = v.y; t[r][c4 + 2] = v.z; t[r][c4 + 3] = v.w;
    }
    __syncthreads();
    #pragma unroll
    for (int i = 0; i < 4; i++) {
        int it = tid + i * 256;
        int n = it >> 4;
        int kc = (it & 15) * 4;
        __half h[4];
        #pragma unroll
        for (int j = 0; j < 4; j++) h[j] = __float2half_rn(t[kc + j][n]);
        *(uint2*)(Th + (size_t)(n0 + n) * Kd + k0 + kc) = *(uint2*)h;
    }
}

// =============== RoPE + fp16 hi/lo split (Q), summing two split-K buffers ===
__global__ void rope_q_h(const float* __restrict__ Q0,
                         const float* __restrict__ cosT,
                         const float* __restrict__ sinT,
                         __half* __restrict__ Xh,
                         __half* __restrict__ Xl)
{
    int idx = blockIdx.x * blockDim.x + threadIdx.x;
    int total = NT * NH * 32;
    if (idx >= total) return;
    int j = idx & 31;
    int hh = (idx >> 5) % NH;
    int t = idx / (32 * NH);
    int s = t & (SS - 1);
    int d = 2 * j;

    const float* p0 = Q0 + (size_t)t * QDIM + hh * HD;
    const float* p1 = p0 + (size_t)NT * QDIM;
    float x0 = p0[d]      + p1[d];
    float x1 = p0[d + 1]  + p1[d + 1];
    float y0 = p0[d + 64] + p1[d + 64];
    float y1 = p0[d + 65] + p1[d + 65];
    const float* cp = cosT + s * HD;
    const float* sp = sinT + s * HD;
    float r0 = x0 * cp[d]      - y0 * sp[d];
    float r1 = x1 * cp[d + 1]  - y1 * sp[d + 1];
    float r2 = y0 * cp[d + 64] + x0 * sp[d + 64];
    float r3 = y1 * cp[d + 65] + x1 * sp[d + 65];

    size_t o0 = (size_t)t * QDIM + hh * HD + d;
    __half h0 = __float2half_rn(r0), h1 = __float2half_rn(r1);
    __half h2 = __float2half_rn(r2), h3 = __float2half_rn(r3);
    __half q0 = __float2half_rn(r0 - __half2float(h0));
    __half q1 = __float2half_rn(r1 - __half2float(h1));
    __half q2 = __float2half_rn(r2 - __half2float(h2));
    __half q3 = __float2half_rn(r3 - __half2float(h3));
    __half hp[2] = {h0, h1};  *(uint32_t*)(Xh + o0) = *(uint32_t*)hp;
    __half lp[2] = {q0, q1};  *(uint32_t*)(Xl + o0) = *(uint32_t*)lp;
    __half hp2[2] = {h2, h3}; *(uint32_t*)(Xh + o0 + 64) = *(uint32_t*)hp2;
    __half lp2[2] = {q2, q3}; *(uint32_t*)(Xl + o0 + 64) = *(uint32_t*)lp2;
}

// ---------------- fp16 2-term flash attention (causal, GQA, 2-stage KV) -----
// smem: Qh 32KB | Ql 32KB | 2 stages x (K 16KB + Vt 16KB) = 128KB
#define ASMEM_BYTES (131072)

__device__ __forceinline__ void attn_load_kv(
    uint32_t st, const __half* Kh, const __half* Vt,
    int b, int g, int kt, int tid)
{
    const int tk0 = b * SS + kt * 64;
    const size_t vrow0 = (size_t)((b * NKV + g) * HD) * SS;
    #pragma unroll 8
    for (int c = tid; c < 2048; c += 256) {
        if (c < 1024) {
            int r = c >> 4, sg = c & 15, half = sg >> 3, sgi = sg & 7;
            const void* src = Kh + (size_t)(tk0 + r) * KDIM + g * HD + half * 64 + sgi * 8;
            uint32_t dst = st + half * 8192 + sw128(r * 128 + sgi * 16);
            cp_async16(dst, src);
        } else {
            int idx = c - 1024;
            int d = idx >> 3, sg = idx & 7;
            const void* src = Vt + vrow0 + (size_t)d * SS + kt * 64 + sg * 8;
            uint32_t dst = st + 16384 + sw128(d * 128 + sg * 16);
            cp_async16(dst, src);
        }
    }
    CP_COMMIT();
}

__global__ __launch_bounds__(256, 1) void attn_mma(
    const __half* __restrict__ Qh, const __half* __restrict__ Ql,
    const __half* __restrict__ Kh, const __half* __restrict__ Vt,
    __half* __restrict__ Oh)
{
    extern __shared__ char smc[];
    const uint32_t sb = smem_u32(smc);
    const int tid = threadIdx.x, wid = tid >> 5, lane = tid & 31;
    const int bid = blockIdx.x;
    const int qb = 15 - (bid >> 6);     // heavy-first
    const int bh = bid & 63;
    const int b = bh >> 5, h = bh & 31, g = h >> 2;
    const int tok0 = b * SS + qb * 128;
    const int KT = 2 * qb + 2;
    const float SCL = 0.08838834764831845f * 1.4426950408889634f;

    #pragma unroll 4
    for (int c = tid; c < 4096; c += 256) {
        int hl = c >> 11, cc = c & 2047;
        int r = cc >> 4, sg = cc & 15, half = sg >> 3, sgi = sg & 7;
        const __half* base = hl ? Ql : Qh;
        const void* src = base + (size_t)(tok0 + r) * QDIM + h * HD + half * 64 + sgi * 8;
        uint32_t dst = sb + hl * 32768 + half * 16384 + sw128(r * 128 + sgi * 16);
        cp_async16(dst, src);
    }
    attn_load_kv(sb + 65536, Kh, Vt, b, g, 0, tid);

    float o[16][4];
    #pragma unroll
    for (int nd = 0; nd < 16; nd++)
        #pragma unroll
        for (int e = 0; e < 4; e++) o[nd][e] = 0.f;
    float m0 = -1e30f, m1 = -1e30f, l0 = 0.f, l1 = 0.f;

    const int qg0 = qb * 128 + wid * 16 + (lane >> 2);
    const int qg1 = qg0 + 8;

    for (int kt = 0; kt < KT; kt++) {
        CP_WAIT0();
        __syncthreads();
        if (kt + 1 < KT)
            attn_load_kv(sb + 65536 + ((kt + 1) & 1) * 32768, Kh, Vt, b, g, kt + 1, tid);

        const uint32_t st = sb + 65536 + (kt & 1) * 32768;
        const bool skip = kt * 64 > qb * 128 + wid * 16 + 15;

        if (!skip) {
            float s[8][4];
            #pragma unroll
            for (int nj = 0; nj < 8; nj++)
                #pragma unroll
                for (int e = 0; e < 4; e++) s[nj][e] = 0.f;

            #pragma unroll
            for (int k16 = 0; k16 < 8; k16++) {
                const int half = k16 >> 2;
                const int cb = (k16 & 3) * 32 + (lane >> 4) * 16;
                const uint32_t qoff = sw128((wid * 16 + (lane & 15)) * 128 + cb);
                uint32_t ah[4], al[4];
                LDSM4(ah, sb + half * 16384 + qoff);
                LDSM4(al, sb + 32768 + half * 16384 + qoff);
                uint32_t bhf[4][4];
                #pragma unroll
                for (int c = 0; c < 4; c++) {
                    const uint32_t koff = sw128((c * 16 + (lane & 15)) * 128 + cb);
                    LDSM4(bhf[c], st + half * 8192 + koff);
                }
                #pragma unroll
                for (int nj = 0; nj < 8; nj++) {
                    const int np = nj >> 1, h2 = nj & 1;
                    MMAH16816(s[nj], ah, bhf[np][h2], bhf[np][2 + h2]);
                }
                #pragma unroll
                for (int nj = 0; nj < 8; nj++) {
                    const int np = nj >> 1, h2 = nj & 1;
                    MMAH16816(s[nj], al, bhf[np][h2], bhf[np][2 + h2]);
                }
            }

            const bool domask = (kt * 64 + 63) > qg0;
            #pragma unroll
            for (int nj = 0; nj < 8; nj++) {
                #pragma unroll
                for (int e = 0; e < 4; e++) s[nj][e] *= SCL;
                if (domask) {
                    const int kc = kt * 64 + nj * 8 + (lane & 3) * 2;
                    if (kc     > qg0) s[nj][0] = -1e30f;
                    if (kc + 1 > qg0) s[nj][1] = -1e30f;
                    if (kc     > qg1) s[nj][2] = -1e30f;
                    if (kc + 1 > qg1) s[nj][3] = -1e30f;
                }
            }
            float mx0 = -1e30f, mx1 = -1e30f;
            #pragma unroll
            for (int nj = 0; nj < 8; nj++) {
                mx0 = fmaxf(mx0, fmaxf(s[nj][0], s[nj][1]));
                mx1 = fmaxf(mx1, fmaxf(s[nj][2], s[nj][3]));
            }
            mx0 = fmaxf(mx0, __shfl_xor_sync(0xffffffffu, mx0, 1));
            mx0 = fmaxf(mx0, __shfl_xor_sync(0xffffffffu, mx0, 2));
            mx1 = fmaxf(mx1, __shfl_xor_sync(0xffffffffu, mx1, 1));
            mx1 = fmaxf(mx1, __shfl_xor_sync(0xffffffffu, mx1, 2));
            const float nm0 = fmaxf(m0, mx0), nm1 = fmaxf(m1, mx1);
            const float c0 = exp2a(m0 - nm0), c1 = exp2a(m1 - nm1);
            float rs0 = 0.f, rs1 = 0.f;
            #pragma unroll
            for (int nj = 0; nj < 8; nj++) {
                s[nj][0] = exp2a(s[nj][0] - nm0);
                s[nj][1] = exp2a(s[nj][1] - nm0);
                s[nj][2] = exp2a(s[nj][2] - nm1);
                s[nj][3] = exp2a(s[nj][3] - nm1);
                rs0 += s[nj][0] + s[nj][1];
                rs1 += s[nj][2] + s[nj][3];
            }
            rs0 += __shfl_xor_sync(0xffffffffu, rs0, 1);
            rs0 += __shfl_xor_sync(0xffffffffu, rs0, 2);
            rs1 += __shfl_xor_sync(0xffffffffu, rs1, 1);
            rs1 += __shfl_xor_sync(0xffffffffu, rs1, 2);
            m0 = nm0; m1 = nm1;
            l0 = l0 * c0 + rs0;
            l1 = l1 * c1 + rs1;
            #pragma unroll
            for (int nd = 0; nd < 16; nd++) {
                o[nd][0] *= c0; o[nd][1] *= c0;
                o[nd][2] *= c1; o[nd][3] *= c1;
            }

            #pragma unroll
            for (int j2 = 0; j2 < 4; j2++) {
                const int n0 = 2 * j2, n1 = 2 * j2 + 1;
                uint32_t aPh[4], aPl[4];
                __half2 t0 = __floats2half2_rn(s[n0][0], s[n0][1]);
                __half2 t1 = __floats2half2_rn(s[n0][2], s[n0][3]);
                __half2 t2 = __floats2half2_rn(s[n1][0], s[n1][1]);
                __half2 t3 = __floats2half2_rn(s[n1][2], s[n1][3]);
                aPh[0] = *(uint32_t*)&t0; aPh[1] = *(uint32_t*)&t1;
                aPh[2] = *(uint32_t*)&t2; aPh[3] = *(uint32_t*)&t3;
                __half2 u0 = __floats2half2_rn(s[n0][0] - __low2float(t0),
                                               s[n0][1] - __high2float(t0));
                __half2 u1 = __floats2half2_rn(s[n0][2] - __low2float(t1),
                                               s[n0][3] - __high2float(t1));
                __half2 u2 = __floats2half2_rn(s[n1][0] - __low2float(t2),
                                               s[n1][1] - __high2float(t2));
                __half2 u3 = __floats2half2_rn(s[n1][2] - __low2float(t3),
                                               s[n1][3] - __high2float(t3));
                aPl[0] = *(uint32_t*)&u0; aPl[1] = *(uint32_t*)&u1;
                aPl[2] = *(uint32_t*)&u2; aPl[3] = *(uint32_t*)&u3;

                #pragma unroll
                for (int c = 0; c < 8; c++) {
                    const uint32_t voff = sw128((c * 16 + (lane & 15)) * 128 + j2 * 32 + (lane >> 4) * 16);
                    uint32_t vh[4];
                    LDSM4(vh, st + 16384 + voff);
                    MMAH16816(o[2 * c],     aPh, vh[0], vh[2]);
                    MMAH16816(o[2 * c + 1], aPh, vh[1], vh[3]);
                    MMAH16816(o[2 * c],     aPl, vh[0], vh[2]);
                    MMAH16816(o[2 * c + 1], aPl, vh[1], vh[3]);
                }
            }
        }
    }

    // epilogue: normalize, single fp16 output (Wo GEMM is 1-term)
    const float il0 = 1.f / l0, il1 = 1.f / l1;
    const int row0g = tok0 + wid * 16 + (lane >> 2);
    #pragma unroll
    for (int nd = 0; nd < 16; nd++) {
        const int col = h * HD + nd * 8 + (lane & 3) * 2;
        __half2 h0 = __floats2half2_rn(o[nd][0] * il0, o[nd][1] * il0);
        __half2 h1 = __floats2half2_rn(o[nd][2] * il1, o[nd][3] * il1);
        *(uint32_t*)(Oh + (size_t)row0g * QDIM + col)       = *(uint32_t*)&h0;
        *(uint32_t*)(Oh + (size_t)(row0g + 8) * QDIM + col) = *(uint32_t*)&h1;
    }
}

// ---------------- launcher ---------------------------------------------------
extern "C" void kernel_launch(void* const* d_in, const int* in_sizes, int n_in,
                              void* d_out, int out_size)
{
    const float* x    = (const float*)d_in[0];
    const float* cosT = (const float*)d_in[1];
    const float* sinT = (const float*)d_in[2];
    const float* Wq   = (const float*)d_in[3];
    const float* Wk   = (const float*)d_in[4];
    const float* Wv   = (const float*)d_in[5];
    const float* Wo   = (const float*)d_in[6];
    float* out = (float*)d_out;

    float* Q;
    __half *xh, *xl, *Wqh, *Wkh, *Wvh, *Woh, *Ah;
    __half *Qah, *Qal, *Kah, *Vt;
    cudaGetSymbolAddress((void**)&Q, g_Q);
    cudaGetSymbolAddress((void**)&xh, g_xh);
    cudaGetSymbolAddress((void**)&xl, g_xl);
    cudaGetSymbolAddress((void**)&Wqh, g_Wqh);
    cudaGetSymbolAddress((void**)&Wkh, g_Wkh);
    cudaGetSymbolAddress((void**)&Wvh, g_Wvh);
    cudaGetSymbolAddress((void**)&Woh, g_Woh);
    cudaGetSymbolAddress((void**)&Ah, g_Ah);
    cudaGetSymbolAddress((void**)&Qah, g_Qah);
    cudaGetSymbolAddress((void**)&Qal, g_Qal);
    cudaGetSymbolAddress((void**)&Kah, g_Kah);
    cudaGetSymbolAddress((void**)&Vt, g_Vt);

    cudaFuncSetAttribute(gemm_fp16x2, cudaFuncAttributeMaxDynamicSharedMemorySize, GSMEM_BYTES);
    cudaFuncSetAttribute(gemm_fp16x1, cudaFuncAttributeMaxDynamicSharedMemorySize, GSMEM1_BYTES);
    cudaFuncSetAttribute(gemm_fp16x1_atomic, cudaFuncAttributeMaxDynamicSharedMemorySize, GSMEM1_BYTES);
    cudaFuncSetAttribute(gemm_k_rope, cudaFuncAttributeMaxDynamicSharedMemorySize, GSMEM_BYTES);
    cudaFuncSetAttribute(gemm_v_t, cudaFuncAttributeMaxDynamicSharedMemorySize, GSMEM_BYTES);
    cudaFuncSetAttribute(attn_mma, cudaFuncAttributeMaxDynamicSharedMemorySize, ASMEM_BYTES);

    // zero-init only the Wo split-K target
    cudaMemsetAsync(out, 0, (size_t)NT * DIM * sizeof(float));

    // conversions
    split_rows_h<<<(NT * DIM / 4 + 255) / 256, 256>>>(x, xh, xl, NT * DIM / 4);
    transpose_h<<<dim3(QDIM / 64, DIM / 64), 256>>>(Wq, Wqh, DIM, QDIM);
    transpose_h<<<dim3(KDIM / 64, DIM / 64), 256>>>(Wk, Wkh, DIM, KDIM);
    transpose_h<<<dim3(KDIM / 64, DIM / 64), 256>>>(Wv, Wvh, DIM, KDIM);
    transpose_h<<<dim3(DIM / 64, QDIM / 64), 256>>>(Wo, Woh, QDIM, DIM);

    // Q projection: 1-term, split-K=2 into two plain-store buffers
    gemm_fp16x1<<<dim3(QDIM / 256, NT / 128, 2), 256, GSMEM1_BYTES>>>(xh, Wqh, Q, NT, QDIM, DIM, 1);
    // K projection (2-term) with fused RoPE -> Kah
    gemm_k_rope<<<dim3(KDIM / 256, NT / 128, 1), 256, GSMEM_BYTES>>>(xh, xl, Wkh, cosT, sinT, Kah, NT, KDIM, DIM);
    // V projection (2-term) with fused transpose -> Vt
    gemm_v_t<<<dim3(KDIM / 256, NT / 128, 1), 256, GSMEM_BYTES>>>(xh, xl, Wvh, Vt, NT, KDIM, DIM);

    // Q: sum split buffers + RoPE + fp16 split
    rope_q_h<<<(NT * NH * 32 + 255) / 256, 256>>>(Q, cosT, sinT, Qah, Qal);

    // fp16 2-term flash attention -> single fp16 output
    attn_mma<<<1024, 256, ASMEM_BYTES>>>(Qah, Qal, Kah, Vt, Ah);

    // Output projection (fp16 1-term, split-K=2, atomic into zeroed out)
    gemm_fp16x1_atomic<<<dim3(DIM / 256, NT / 128, 2), 256, GSMEM1_BYTES>>>(Ah, Woh, out, NT, DIM, QDIM);
}

// round 17
// speedup vs baseline: 1.4256x; 1.0096x over previous
#include <cuda_runtime.h>
#include <cuda_bf16.h>
#include <cuda_fp16.h>
#include <math.h>
#include <stdint.h>

// Problem constants
#define BB   2
#define SS   2048
#define DIM  4096
#define NH   32
#define NKV  8
#define HD   128
#define NT   (BB*SS)          // 4096 tokens
#define QDIM (NH*HD)          // 4096
#define KDIM (NKV*HD)         // 1024

// ---------------- scratch (device globals; no allocation allowed) ----------
__device__ __half g_xh[NT * DIM];
__device__ __half g_xl[NT * DIM];
__device__ __half g_Wqh[QDIM * DIM];     // transposed [N][K]
__device__ __half g_Wkh[KDIM * DIM];
__device__ __half g_Wvh[KDIM * DIM];
__device__ __half g_Woh[DIM * QDIM];
__device__ __half g_Ah[NT * QDIM];       // attention out (fp16, single)
__device__ __half g_Qah[NT * QDIM];      // Q hi (exact split, RoPE'd)
__device__ __half g_Qal[NT * QDIM];      // Q lo
__device__ __half g_Kah[NT * KDIM];      // K single fp16 (RoPE'd)
__device__ __half g_Vt[BB * NKV * HD * SS];  // V transposed [b][g][d][s]

// ======================= PTX helpers =======================
__device__ __forceinline__ uint32_t smem_u32(const void* p) {
    uint32_t a;
    asm("{ .reg .u64 t; cvta.to.shared.u64 t, %1; cvt.u32.u64 %0, t; }" : "=r"(a) : "l"(p));
    return a;
}
__device__ __forceinline__ void cp_async16(uint32_t dst, const void* src) {
    asm volatile("cp.async.cg.shared.global [%0], [%1], 16;" :: "r"(dst), "l"(src));
}
#define CP_COMMIT() asm volatile("cp.async.commit_group;" ::: "memory")
#define CP_WAIT0()  asm volatile("cp.async.wait_group 0;" ::: "memory")

__device__ __forceinline__ uint32_t sw128(uint32_t b) { return b ^ ((b >> 3) & 0x70); }

__device__ __forceinline__ float exp2a(float x) {
    float r;
    asm("ex2.approx.f32 %0, %1;" : "=f"(r) : "f"(x));
    return r;
}

#define LDSM4(r, addr) \
    asm volatile("ldmatrix.sync.aligned.m8n8.x4.shared.b16 {%0,%1,%2,%3}, [%4];" \
        : "=r"((r)[0]), "=r"((r)[1]), "=r"((r)[2]), "=r"((r)[3]) : "r"(addr))

#define MMAH16816(c, a, b0, b1) \
    asm volatile("mma.sync.aligned.m16n8k16.row.col.f32.f16.f16.f32 " \
        "{%0,%1,%2,%3}, {%4,%5,%6,%7}, {%8,%9}, {%0,%1,%2,%3};" \
        : "+f"((c)[0]), "+f"((c)[1]), "+f"((c)[2]), "+f"((c)[3]) \
        : "r"((a)[0]), "r"((a)[1]), "r"((a)[2]), "r"((a)[3]), "r"(b0), "r"(b1))

// =============== fp16 2-term HMMA GEMM core (2-stage, 128x256 tile) =========
#define GSMEM_BYTES (2 * 65536)

__device__ __forceinline__ void load_stage_part(
    uint32_t buf, const __half* Ah, const __half* Al, const __half* Bh,
    int row0, int col0, int K, int kchunk, int tid, int part)
{
    #pragma unroll
    for (int j = 0; j < 4; j++) {
        const int c = tid + part * 1024 + j * 256;
        if (c < 1024) {
            const int r = c >> 3, sg = c & 7;
            const uint32_t dst = buf + sw128(r * 128 + sg * 16);
            cp_async16(dst, Ah + (size_t)(row0 + r) * K + kchunk * 64 + sg * 8);
        } else if (c < 2048) {
            const int idx = c - 1024;
            const int r = idx >> 3, sg = idx & 7;
            const uint32_t dst = buf + 16384 + sw128(r * 128 + sg * 16);
            cp_async16(dst, Al + (size_t)(row0 + r) * K + kchunk * 64 + sg * 8);
        } else {
            const int idx = c - 2048;
            const int r = idx >> 3, sg = idx & 7;      // r 0..255
            const uint32_t dst = buf + 32768 + sw128(r * 128 + sg * 16);
            cp_async16(dst, Bh + (size_t)(col0 + r) * K + kchunk * 64 + sg * 8);
        }
    }
}

// 2-term mainloop; results in acc[4][8][4].
// single-group-ahead pipeline -> wait at loop head MUST be wait_group 0.
#define GEMM_MAINLOOP(Ah, Al, Bh, row0, col0, K, kb, KT)                        \
    {                                                                           \
        _Pragma("unroll")                                                       \
        for (int p = 0; p < 4; p++)                                             \
            load_stage_part(sb, Ah, Al, Bh, row0, col0, K, kb, tid, p);         \
        CP_COMMIT();                                                            \
        for (int it = 0; it < KT; it++) {                                       \
            const uint32_t buf = sb + (it & 1) * 65536;                         \
            const uint32_t nbuf = sb + ((it + 1) & 1) * 65536;                  \
            const bool more = (it + 1 < KT);                                    \
            CP_WAIT0();                                                         \
            __syncthreads();                                                    \
            const uint32_t aHb = buf;                                           \
            const uint32_t aLb = buf + 16384;                                   \
            const uint32_t bHb = buf + 32768;                                   \
            _Pragma("unroll")                                                   \
            for (int k16 = 0; k16 < 4; k16++) {                                 \
                if (more) {                                                     \
                    load_stage_part(nbuf, Ah, Al, Bh, row0, col0, K, kb + it + 1, tid, k16); \
                    if (k16 == 3) CP_COMMIT();                                  \
                }                                                               \
                const int colb = k16 * 32 + (lane >> 4) * 16;                   \
                uint32_t ahf[4][4], alf[4][4];                                  \
                _Pragma("unroll")                                               \
                for (int mi = 0; mi < 4; mi++) {                                \
                    const uint32_t off = sw128((wm0 + mi * 16 + (lane & 15)) * 128 + colb); \
                    LDSM4(ahf[mi], aHb + off);                                  \
                    LDSM4(alf[mi], aLb + off);                                  \
                }                                                               \
                _Pragma("unroll")                                               \
                for (int hb = 0; hb < 2; hb++) {                                \
                    uint32_t bh[2][4];                                          \
                    _Pragma("unroll")                                           \
                    for (int np = 0; np < 2; np++) {                            \
                        const uint32_t off =                                    \
                            sw128((wn0 + hb * 32 + np * 16 + (lane & 15)) * 128 + colb); \
                        LDSM4(bh[np], bHb + off);                               \
                    }                                                           \
                    _Pragma("unroll")                                           \
                    for (int mi = 0; mi < 4; mi++)                              \
                        _Pragma("unroll")                                       \
                        for (int nj = 0; nj < 4; nj++) {                        \
                            const int np = nj >> 1, hq = nj & 1;                \
                            MMAH16816(acc[mi][hb * 4 + nj], ahf[mi], bh[np][hq], bh[np][2 + hq]); \
                        }                                                       \
                    _Pragma("unroll")                                           \
                    for (int mi = 0; mi < 4; mi++)                              \
                        _Pragma("unroll")                                       \
                        for (int nj = 0; nj < 4; nj++) {                        \
                            const int np = nj >> 1, hq = nj & 1;                \
                            MMAH16816(acc[mi][hb * 4 + nj], alf[mi], bh[np][hq], bh[np][2 + hq]); \
                        }                                                       \
                }                                                               \
            }                                                                   \
        }                                                                       \
    }

// ---- 1-term variant (A single): stage = Ah 16KB | Bh 32KB = 48KB ----
#define GSMEM1_STAGE 49152
#define GSMEM1_BYTES (2 * GSMEM1_STAGE)

__device__ __forceinline__ void load_stage_part_1t(
    uint32_t buf, const __half* Ah, const __half* Bh,
    int row0, int col0, int K, int kchunk, int tid, int part)
{
    #pragma unroll
    for (int j = 0; j < 3; j++) {
        const int c = tid + part * 768 + j * 256;
        if (c < 1024) {
            const int r = c >> 3, sg = c & 7;
            const uint32_t dst = buf + sw128(r * 128 + sg * 16);
            cp_async16(dst, Ah + (size_t)(row0 + r) * K + kchunk * 64 + sg * 8);
        } else {
            const int idx = c - 1024;
            const int r = idx >> 3, sg = idx & 7;      // r 0..255
            const uint32_t dst = buf + 16384 + sw128(r * 128 + sg * 16);
            cp_async16(dst, Bh + (size_t)(col0 + r) * K + kchunk * 64 + sg * 8);
        }
    }
}

#define GEMM_MAINLOOP_1T(Ah, Bh, row0, col0, K, kb, KT)                         \
    {                                                                           \
        _Pragma("unroll")                                                       \
        for (int p = 0; p < 4; p++)                                             \
            load_stage_part_1t(sb, Ah, Bh, row0, col0, K, kb, tid, p);          \
        CP_COMMIT();                                                            \
        for (int it = 0; it < KT; it++) {                                       \
            const uint32_t buf = sb + (it & 1) * GSMEM1_STAGE;                  \
            const uint32_t nbuf = sb + ((it + 1) & 1) * GSMEM1_STAGE;           \
            const bool more = (it + 1 < KT);                                    \
            CP_WAIT0();                                                         \
            __syncthreads();                                                    \
            const uint32_t aHb = buf;                                           \
            const uint32_t bHb = buf + 16384;                                   \
            _Pragma("unroll")                                                   \
            for (int k16 = 0; k16 < 4; k16++) {                                 \
                if (more) {                                                     \
                    load_stage_part_1t(nbuf, Ah, Bh, row0, col0, K, kb + it + 1, tid, k16); \
                    if (k16 == 3) CP_COMMIT();                                  \
                }                                                               \
                const int colb = k16 * 32 + (lane >> 4) * 16;                   \
                uint32_t ahf[4][4];                                             \
                _Pragma("unroll")                                               \
                for (int mi = 0; mi < 4; mi++) {                                \
                    const uint32_t off = sw128((wm0 + mi * 16 + (lane & 15)) * 128 + colb); \
                    LDSM4(ahf[mi], aHb + off);                                  \
                }                                                               \
                _Pragma("unroll")                                               \
                for (int hb = 0; hb < 2; hb++) {                                \
                    uint32_t bh[2][4];                                          \
                    _Pragma("unroll")                                           \
                    for (int np = 0; np < 2; np++) {                            \
                        const uint32_t off =                                    \
                            sw128((wn0 + hb * 32 + np * 16 + (lane & 15)) * 128 + colb); \
                        LDSM4(bh[np], bHb + off);                               \
                    }                                                           \
                    _Pragma("unroll")                                           \
                    for (int mi = 0; mi < 4; mi++)                              \
                        _Pragma("unroll")                                       \
                        for (int nj = 0; nj < 4; nj++) {                        \
                            const int np = nj >> 1, hq = nj & 1;                \
                            MMAH16816(acc[mi][hb * 4 + nj], ahf[mi], bh[np][hq], bh[np][2 + hq]); \
                        }                                                       \
                }                                                               \
            }                                                                   \
        }                                                                       \
    }

// 1-term GEMM with atomic accumulation (Wo split-K into zeroed out)
__global__ __launch_bounds__(256, 1) void gemm_fp16x1_atomic(
    const __half* __restrict__ Ah, const __half* __restrict__ Bh,
    float* __restrict__ C, int M, int N, int K)
{
    extern __shared__ char smc[];
    const uint32_t sb = smem_u32(smc);
    const int tid = threadIdx.x;
    const int wid = tid >> 5;
    const int lane = tid & 31;
    const int row0 = blockIdx.y * 128;
    const int col0 = blockIdx.x * 256;
    const int nz = gridDim.z;
    const int K2 = K / nz;
    const int kb = blockIdx.z * (K2 / 64);
    const int wm0 = (wid >> 2) * 64;
    const int wn0 = (wid & 3) * 64;

    float acc[4][8][4];
    #pragma unroll
    for (int i = 0; i < 4; i++)
        #pragma unroll
        for (int j = 0; j < 8; j++)
            #pragma unroll
            for (int r = 0; r < 4; r++) acc[i][j][r] = 0.f;

    const int KT = K2 / 64;
    GEMM_MAINLOOP_1T(Ah, Bh, row0, col0, K, kb, KT);

    #pragma unroll
    for (int mi = 0; mi < 4; mi++) {
        #pragma unroll
        for (int nj = 0; nj < 8; nj++) {
            const int row = row0 + wm0 + mi * 16 + (lane >> 2);
            const int col = col0 + wn0 + nj * 8 + (lane & 3) * 2;
            float* p0 = C + (size_t)row * N + col;
            float* p1 = C + (size_t)(row + 8) * N + col;
            atomicAdd(p0,     acc[mi][nj][0]);
            atomicAdd(p0 + 1, acc[mi][nj][1]);
            atomicAdd(p1,     acc[mi][nj][2]);
            atomicAdd(p1 + 1, acc[mi][nj][3]);
        }
    }
}

// Q-projection GEMM (1-term) with fused RoPE + fp16 hi/lo split epilogue
// nz=1 only. Epilogue stages fp32 tile [128][256] = 128KB in smem.
#define GQSMEM_BYTES 131072
__global__ __launch_bounds__(256, 1) void gemm_q_rope(
    const __half* __restrict__ Ah, const __half* __restrict__ Bh,
    const float* __restrict__ cosT, const float* __restrict__ sinT,
    __half* __restrict__ Qh, __half* __restrict__ Ql, int M, int N, int K)
{
    extern __shared__ char smc[];
    const uint32_t sb = smem_u32(smc);
    const int tid = threadIdx.x;
    const int wid = tid >> 5;
    const int lane = tid & 31;
    const int row0 = blockIdx.y * 128;
    const int col0 = blockIdx.x * 256;
    const int kb = 0;
    const int wm0 = (wid >> 2) * 64;
    const int wn0 = (wid & 3) * 64;

    float acc[4][8][4];
    #pragma unroll
    for (int i = 0; i < 4; i++)
        #pragma unroll
        for (int j = 0; j < 8; j++)
            #pragma unroll
            for (int r = 0; r < 4; r++) acc[i][j][r] = 0.f;

    const int KT = K / 64;
    GEMM_MAINLOOP_1T(Ah, Bh, row0, col0, K, kb, KT);

    // stage acc tile to smem fp32 [128][256] (128KB)
    __syncthreads();
    float* tile = (float*)smc;
    #pragma unroll
    for (int mi = 0; mi < 4; mi++) {
        #pragma unroll
        for (int nj = 0; nj < 8; nj++) {
            const int r = wm0 + mi * 16 + (lane >> 2);
            const int c = wn0 + nj * 8 + (lane & 3) * 2;
            *(float2*)&tile[r * 256 + c]       = make_float2(acc[mi][nj][0], acc[mi][nj][1]);
            *(float2*)&tile[(r + 8) * 256 + c] = make_float2(acc[mi][nj][2], acc[mi][nj][3]);
        }
    }
    __syncthreads();

    // rope + hi/lo split + write: 8192 units (128 rows x 2 heads x 32 d-pairs)
    #pragma unroll 4
    for (int i = 0; i < 32; i++) {
        const int idx = tid + i * 256;
        const int r = idx >> 6;
        const int rest = idx & 63;
        const int head2 = rest >> 5;
        const int d = (rest & 31) * 2;
        const int tok = row0 + r;
        const int s = tok & (SS - 1);
        const int cbase = head2 * 128;
        float x0 = tile[r * 256 + cbase + d];
        float x1 = tile[r * 256 + cbase + d + 1];
        float y0 = tile[r * 256 + cbase + d + 64];
        float y1 = tile[r * 256 + cbase + d + 65];
        const float* cp = cosT + s * HD;
        const float* sp = sinT + s * HD;
        float r0 = x0 * cp[d]      - y0 * sp[d];
        float r1 = x1 * cp[d + 1]  - y1 * sp[d + 1];
        float r2 = y0 * cp[d + 64] + x0 * sp[d + 64];
        float r3 = y1 * cp[d + 65] + x1 * sp[d + 65];

        size_t o = (size_t)tok * QDIM + col0 + cbase + d;
        __half h0 = __float2half_rn(r0), h1 = __float2half_rn(r1);
        __half h2 = __float2half_rn(r2), h3 = __float2half_rn(r3);
        __half q0 = __float2half_rn(r0 - __half2float(h0));
        __half q1 = __float2half_rn(r1 - __half2float(h1));
        __half q2 = __float2half_rn(r2 - __half2float(h2));
        __half q3 = __float2half_rn(r3 - __half2float(h3));
        __half hp[2]  = {h0, h1}; *(uint32_t*)(Qh + o)      = *(uint32_t*)hp;
        __half lp[2]  = {q0, q1}; *(uint32_t*)(Ql + o)      = *(uint32_t*)lp;
        __half hp2[2] = {h2, h3}; *(uint32_t*)(Qh + o + 64) = *(uint32_t*)hp2;
        __half lp2[2] = {q2, q3}; *(uint32_t*)(Ql + o + 64) = *(uint32_t*)lp2;
    }
}

// K-projection GEMM (2-term) with fused RoPE epilogue -> Kah fp16 (nz=1 only)
__global__ __launch_bounds__(256, 1) void gemm_k_rope(
    const __half* __restrict__ Ah, const __half* __restrict__ Al,
    const __half* __restrict__ Bh,
    const float* __restrict__ cosT, const float* __restrict__ sinT,
    __half* __restrict__ Kout, int M, int N, int K)
{
    extern __shared__ char smc[];
    const uint32_t sb = smem_u32(smc);
    const int tid = threadIdx.x;
    const int wid = tid >> 5;
    const int lane = tid & 31;
    const int row0 = blockIdx.y * 128;
    const int col0 = blockIdx.x * 256;
    const int kb = 0;
    const int wm0 = (wid >> 2) * 64;
    const int wn0 = (wid & 3) * 64;

    float acc[4][8][4];
    #pragma unroll
    for (int i = 0; i < 4; i++)
        #pragma unroll
        for (int j = 0; j < 8; j++)
            #pragma unroll
            for (int r = 0; r < 4; r++) acc[i][j][r] = 0.f;

    const int KT = K / 64;
    GEMM_MAINLOOP(Ah, Al, Bh, row0, col0, K, kb, KT);

    __syncthreads();
    float* tile = (float*)smc;
    #pragma unroll
    for (int mi = 0; mi < 4; mi++) {
        #pragma unroll
        for (int nj = 0; nj < 8; nj++) {
            const int r = wm0 + mi * 16 + (lane >> 2);
            const int c = wn0 + nj * 8 + (lane & 3) * 2;
            *(float2*)&tile[r * 256 + c]       = make_float2(acc[mi][nj][0], acc[mi][nj][1]);
            *(float2*)&tile[(r + 8) * 256 + c] = make_float2(acc[mi][nj][2], acc[mi][nj][3]);
        }
    }
    __syncthreads();

    #pragma unroll 4
    for (int i = 0; i < 32; i++) {
        const int idx = tid + i * 256;
        const int r = idx >> 6;
        const int rest = idx & 63;
        const int head2 = rest >> 5;
        const int d = (rest & 31) * 2;
        const int tok = row0 + r;
        const int s = tok & (SS - 1);
        const int cbase = head2 * 128;
        float x0 = tile[r * 256 + cbase + d];
        float x1 = tile[r * 256 + cbase + d + 1];
        float y0 = tile[r * 256 + cbase + d + 64];
        float y1 = tile[r * 256 + cbase + d + 65];
        const float* cp = cosT + s * HD;
        const float* sp = sinT + s * HD;
        float r0 = x0 * cp[d]      - y0 * sp[d];
        float r1 = x1 * cp[d + 1]  - y1 * sp[d + 1];
        float r2 = y0 * cp[d + 64] + x0 * sp[d + 64];
        float r3 = y1 * cp[d + 65] + x1 * sp[d + 65];
        const int gcol = col0 + cbase;
        const int g = gcol >> 7;
        size_t o = (size_t)tok * KDIM + g * HD + d;
        __half hp[2]  = {__float2half_rn(r0), __float2half_rn(r1)};
        __half hp2[2] = {__float2half_rn(r2), __float2half_rn(r3)};
        *(uint32_t*)(Kout + o)      = *(uint32_t*)hp;
        *(uint32_t*)(Kout + o + 64) = *(uint32_t*)hp2;
    }
}

// V-projection GEMM (1-term) with fused transpose epilogue -> Vt fp16 (nz=1)
#define VT_PAD 132
__global__ __launch_bounds__(256, 1) void gemm_v_t(
    const __half* __restrict__ Ah, const __half* __restrict__ Bh,
    __half* __restrict__ Vt, int M, int N, int K)
{
    extern __shared__ char smc[];
    const uint32_t sb = smem_u32(smc);
    const int tid = threadIdx.x;
    const int wid = tid >> 5;
    const int lane = tid & 31;
    const int row0 = blockIdx.y * 128;
    const int col0 = blockIdx.x * 256;
    const int kb = 0;
    const int wm0 = (wid >> 2) * 64;
    const int wn0 = (wid & 3) * 64;

    float acc[4][8][4];
    #pragma unroll
    for (int i = 0; i < 4; i++)
        #pragma unroll
        for (int j = 0; j < 8; j++)
            #pragma unroll
            for (int r = 0; r < 4; r++) acc[i][j][r] = 0.f;

    const int KT = K / 64;
    GEMM_MAINLOOP_1T(Ah, Bh, row0, col0, K, kb, KT);

    __syncthreads();
    __half* ht = (__half*)smc;
    #pragma unroll
    for (int mi = 0; mi < 4; mi++) {
        #pragma unroll
        for (int nj = 0; nj < 8; nj++) {
            const int r = wm0 + mi * 16 + (lane >> 2);
            const int c = wn0 + nj * 8 + (lane & 3) * 2;
            ht[c * VT_PAD + r]           = __float2half_rn(acc[mi][nj][0]);
            ht[(c + 1) * VT_PAD + r]     = __float2half_rn(acc[mi][nj][1]);
            ht[c * VT_PAD + r + 8]       = __float2half_rn(acc[mi][nj][2]);
            ht[(c + 1) * VT_PAD + r + 8] = __float2half_rn(acc[mi][nj][3]);
        }
    }
    __syncthreads();

    const int gcol = col0 + tid;
    const int g = gcol >> 7;
    const int d = gcol & 127;
    const int b = row0 >> 11;
    const int sbase = row0 & (SS - 1);
    __half* dst = Vt + ((size_t)((b * NKV + g) * HD) + d) * SS + sbase;
    const __half* srcc = ht + tid * VT_PAD;
    #pragma unroll 8
    for (int i = 0; i < 32; i++)
        *(uint2*)(dst + i * 4) = *(const uint2*)(srcc + i * 4);
}

// =============== fp32 -> fp16 hi/lo split (row-major) ===========
__global__ void split_rows_h(const float* __restrict__ X,
                             __half* __restrict__ Xh,
                             __half* __restrict__ Xl, int total4)
{
    int i = blockIdx.x * blockDim.x + threadIdx.x;
    if (i >= total4) return;
    float4 v = *(const float4*)(X + (size_t)i * 4);
    __half h[4], l[4];
    float vv[4] = {v.x, v.y, v.z, v.w};
    #pragma unroll
    for (int j = 0; j < 4; j++) {
        h[j] = __float2half_rn(vv[j]);
        l[j] = __float2half_rn(vv[j] - __half2float(h[j]));
    }
    *(uint2*)(Xh + (size_t)i * 4) = *(uint2*)h;
    *(uint2*)(Xl + (size_t)i * 4) = *(uint2*)l;
}

// =============== transpose + fp16 quantize: W[K,N] fp32 -> T [N,K] fp16 =====
__global__ __launch_bounds__(256) void transpose_h(
    const float* __restrict__ W, __half* __restrict__ Th, int Kd, int Nd)
{
    __shared__ float t[64][65];
    const int n0 = blockIdx.x * 64, k0 = blockIdx.y * 64;
    const int tid = threadIdx.x;
    #pragma unroll
    for (int i = 0; i < 4; i++) {
        int it = tid + i * 256;
        int r = it >> 4;
        int c4 = (it & 15) * 4;
        float4 v = *(const float4*)(W + (size_t)(k0 + r) * Nd + n0 + c4);
        t[r][c4] = v.x; t[r][c4 + 1] = v.y; t[r][c4 + 2] = v.z; t[r][c4 + 3] = v.w;
    }
    __syncthreads();
    #pragma unroll
    for (int i = 0; i < 4; i++) {
        int it = tid + i * 256;
        int n = it >> 4;
        int kc = (it & 15) * 4;
        __half h[4];
        #pragma unroll
        for (int j = 0; j < 4; j++) h[j] = __float2half_rn(t[kc + j][n]);
        *(uint2*)(Th + (size_t)(n0 + n) * Kd + k0 + kc) = *(uint2*)h;
    }
}

// ---------------- fp16 2-term flash attention (causal, GQA, 2-stage KV) -----
// smem: Qh 32KB | Ql 32KB | 2 stages x (K 16KB + Vt 16KB) = 128KB
#define ASMEM_BYTES (131072)

__device__ __forceinline__ void attn_load_kv(
    uint32_t st, const __half* Kh, const __half* Vt,
    int b, int g, int kt, int tid)
{
    const int tk0 = b * SS + kt * 64;
    const size_t vrow0 = (size_t)((b * NKV + g) * HD) * SS;
    #pragma unroll 8
    for (int c = tid; c < 2048; c += 256) {
        if (c < 1024) {
            int r = c >> 4, sg = c & 15, half = sg >> 3, sgi = sg & 7;
            const void* src = Kh + (size_t)(tk0 + r) * KDIM + g * HD + half * 64 + sgi * 8;
            uint32_t dst = st + half * 8192 + sw128(r * 128 + sgi * 16);
            cp_async16(dst, src);
        } else {
            int idx = c - 1024;
            int d = idx >> 3, sg = idx & 7;
            const void* src = Vt + vrow0 + (size_t)d * SS + kt * 64 + sg * 8;
            uint32_t dst = st + 16384 + sw128(d * 128 + sg * 16);
            cp_async16(dst, src);
        }
    }
    CP_COMMIT();
}

__global__ __launch_bounds__(256, 1) void attn_mma(
    const __half* __restrict__ Qh, const __half* __restrict__ Ql,
    const __half* __restrict__ Kh, const __half* __restrict__ Vt,
    __half* __restrict__ Oh)
{
    extern __shared__ char smc[];
    const uint32_t sb = smem_u32(smc);
    const int tid = threadIdx.x, wid = tid >> 5, lane = tid & 31;
    const int bid = blockIdx.x;
    const int qb = 15 - (bid >> 6);     // heavy-first
    const int bh = bid & 63;
    const int b = bh >> 5, h = bh & 31, g = h >> 2;
    const int tok0 = b * SS + qb * 128;
    const int KT = 2 * qb + 2;
    const float SCL = 0.08838834764831845f * 1.4426950408889634f;

    #pragma unroll 4
    for (int c = tid; c < 4096; c += 256) {
        int hl = c >> 11, cc = c & 2047;
        int r = cc >> 4, sg = cc & 15, half = sg >> 3, sgi = sg & 7;
        const __half* base = hl ? Ql : Qh;
        const void* src = base + (size_t)(tok0 + r) * QDIM + h * HD + half * 64 + sgi * 8;
        uint32_t dst = sb + hl * 32768 + half * 16384 + sw128(r * 128 + sgi * 16);
        cp_async16(dst, src);
    }
    attn_load_kv(sb + 65536, Kh, Vt, b, g, 0, tid);

    float o[16][4];
    #pragma unroll
    for (int nd = 0; nd < 16; nd++)
        #pragma unroll
        for (int e = 0; e < 4; e++) o[nd][e] = 0.f;
    float m0 = -1e30f, m1 = -1e30f, l0 = 0.f, l1 = 0.f;

    const int qg0 = qb * 128 + wid * 16 + (lane >> 2);
    const int qg1 = qg0 + 8;

    for (int kt = 0; kt < KT; kt++) {
        CP_WAIT0();
        __syncthreads();
        if (kt + 1 < KT)
            attn_load_kv(sb + 65536 + ((kt + 1) & 1) * 32768, Kh, Vt, b, g, kt + 1, tid);

        const uint32_t st = sb + 65536 + (kt & 1) * 32768;
        const bool skip = kt * 64 > qb * 128 + wid * 16 + 15;

        if (!skip) {
            float s[8][4];
            #pragma unroll
            for (int nj = 0; nj < 8; nj++)
                #pragma unroll
                for (int e = 0; e < 4; e++) s[nj][e] = 0.f;

            #pragma unroll
            for (int k16 = 0; k16 < 8; k16++) {
                const int half = k16 >> 2;
                const int cb = (k16 & 3) * 32 + (lane >> 4) * 16;
                const uint32_t qoff = sw128((wid * 16 + (lane & 15)) * 128 + cb);
                uint32_t ah[4], al[4];
                LDSM4(ah, sb + half * 16384 + qoff);
                LDSM4(al, sb + 32768 + half * 16384 + qoff);
                uint32_t bhf[4][4];
                #pragma unroll
                for (int c = 0; c < 4; c++) {
                    const uint32_t koff = sw128((c * 16 + (lane & 15)) * 128 + cb);
                    LDSM4(bhf[c], st + half * 8192 + koff);
                }
                #pragma unroll
                for (int nj = 0; nj < 8; nj++) {
                    const int np = nj >> 1, h2 = nj & 1;
                    MMAH16816(s[nj], ah, bhf[np][h2], bhf[np][2 + h2]);
                }
                #pragma unroll
                for (int nj = 0; nj < 8; nj++) {
                    const int np = nj >> 1, h2 = nj & 1;
                    MMAH16816(s[nj], al, bhf[np][h2], bhf[np][2 + h2]);
                }
            }

            const bool domask = (kt * 64 + 63) > qg0;
            #pragma unroll
            for (int nj = 0; nj < 8; nj++) {
                #pragma unroll
                for (int e = 0; e < 4; e++) s[nj][e] *= SCL;
                if (domask) {
                    const int kc = kt * 64 + nj * 8 + (lane & 3) * 2;
                    if (kc     > qg0) s[nj][0] = -1e30f;
                    if (kc + 1 > qg0) s[nj][1] = -1e30f;
                    if (kc     > qg1) s[nj][2] = -1e30f;
                    if (kc + 1 > qg1) s[nj][3] = -1e30f;
                }
            }
            float mx0 = -1e30f, mx1 = -1e30f;
            #pragma unroll
            for (int nj = 0; nj < 8; nj++) {
                mx0 = fmaxf(mx0, fmaxf(s[nj][0], s[nj][1]));
                mx1 = fmaxf(mx1, fmaxf(s[nj][2], s[nj][3]));
            }
            mx0 = fmaxf(mx0, __shfl_xor_sync(0xffffffffu, mx0, 1));
            mx0 = fmaxf(mx0, __shfl_xor_sync(0xffffffffu, mx0, 2));
            mx1 = fmaxf(mx1, __shfl_xor_sync(0xffffffffu, mx1, 1));
            mx1 = fmaxf(mx1, __shfl_xor_sync(0xffffffffu, mx1, 2));
            const float nm0 = fmaxf(m0, mx0), nm1 = fmaxf(m1, mx1);
            const float c0 = exp2a(m0 - nm0), c1 = exp2a(m1 - nm1);
            float rs0 = 0.f, rs1 = 0.f;
            #pragma unroll
            for (int nj = 0; nj < 8; nj++) {
                s[nj][0] = exp2a(s[nj][0] - nm0);
                s[nj][1] = exp2a(s[nj][1] - nm0);
                s[nj][2] = exp2a(s[nj][2] - nm1);
                s[nj][3] = exp2a(s[nj][3] - nm1);
                rs0 += s[nj][0] + s[nj][1];
                rs1 += s[nj][2] + s[nj][3];
            }
            rs0 += __shfl_xor_sync(0xffffffffu, rs0, 1);
            rs0 += __shfl_xor_sync(0xffffffffu, rs0, 2);
            rs1 += __shfl_xor_sync(0xffffffffu, rs1, 1);
            rs1 += __shfl_xor_sync(0xffffffffu, rs1, 2);
            m0 = nm0; m1 = nm1;
            l0 = l0 * c0 + rs0;
            l1 = l1 * c1 + rs1;
            #pragma unroll
            for (int nd = 0; nd < 16; nd++) {
                o[nd][0] *= c0; o[nd][1] *= c0;
                o[nd][2] *= c1; o[nd][3] *= c1;
            }

            #pragma unroll
            for (int j2 = 0; j2 < 4; j2++) {
                const int n0 = 2 * j2, n1 = 2 * j2 + 1;
                uint32_t aPh[4], aPl[4];
                __half2 t0 = __floats2half2_rn(s[n0][0], s[n0][1]);
                __half2 t1 = __floats2half2_rn(s[n0][2], s[n0][3]);
                __half2 t2 = __floats2half2_rn(s[n1][0], s[n1][1]);
                __half2 t3 = __floats2half2_rn(s[n1][2], s[n1][3]);
                aPh[0] = *(uint32_t*)&t0; aPh[1] = *(uint32_t*)&t1;
                aPh[2] = *(uint32_t*)&t2; aPh[3] = *(uint32_t*)&t3;
                __half2 u0 = __floats2half2_rn(s[n0][0] - __low2float(t0),
                                               s[n0][1] - __high2float(t0));
                __half2 u1 = __floats2half2_rn(s[n0][2] - __low2float(t1),
                                               s[n0][3] - __high2float(t1));
                __half2 u2 = __floats2half2_rn(s[n1][0] - __low2float(t2),
                                               s[n1][1] - __high2float(t2));
                __half2 u3 = __floats2half2_rn(s[n1][2] - __low2float(t3),
                                               s[n1][3] - __high2float(t3));
                aPl[0] = *(uint32_t*)&u0; aPl[1] = *(uint32_t*)&u1;
                aPl[2] = *(uint32_t*)&u2; aPl[3] = *(uint32_t*)&u3;

                #pragma unroll
                for (int c = 0; c < 8; c++) {
                    const uint32_t voff = sw128((c * 16 + (lane & 15)) * 128 + j2 * 32 + (lane >> 4) * 16);
                    uint32_t vh[4];
                    LDSM4(vh, st + 16384 + voff);
                    MMAH16816(o[2 * c],     aPh, vh[0], vh[2]);
                    MMAH16816(o[2 * c + 1], aPh, vh[1], vh[3]);
                    MMAH16816(o[2 * c],     aPl, vh[0], vh[2]);
                    MMAH16816(o[2 * c + 1], aPl, vh[1], vh[3]);
                }
            }
        }
    }

    // epilogue: normalize, single fp16 output (Wo GEMM is 1-term)
    const float il0 = 1.f / l0, il1 = 1.f / l1;
    const int row0g = tok0 + wid * 16 + (lane >> 2);
    #pragma unroll
    for (int nd = 0; nd < 16; nd++) {
        const int col = h * HD + nd * 8 + (lane & 3) * 2;
        __half2 h0 = __floats2half2_rn(o[nd][0] * il0, o[nd][1] * il0);
        __half2 h1 = __floats2half2_rn(o[nd][2] * il1, o[nd][3] * il1);
        *(uint32_t*)(Oh + (size_t)row0g * QDIM + col)       = *(uint32_t*)&h0;
        *(uint32_t*)(Oh + (size_t)(row0g + 8) * QDIM + col) = *(uint32_t*)&h1;
    }
}

// ---------------- launcher ---------------------------------------------------
extern "C" void kernel_launch(void* const* d_in, const int* in_sizes, int n_in,
                              void* d_out, int out_size)
{
    const float* x    = (const float*)d_in[0];
    const float* cosT = (const float*)d_in[1];
    const float* sinT = (const float*)d_in[2];
    const float* Wq   = (const float*)d_in[3];
    const float* Wk   = (const float*)d_in[4];
    const float* Wv   = (const float*)d_in[5];
    const float* Wo   = (const float*)d_in[6];
    float* out = (float*)d_out;

    __half *xh, *xl, *Wqh, *Wkh, *Wvh, *Woh, *Ah;
    __half *Qah, *Qal, *Kah, *Vt;
    cudaGetSymbolAddress((void**)&xh, g_xh);
    cudaGetSymbolAddress((void**)&xl, g_xl);
    cudaGetSymbolAddress((void**)&Wqh, g_Wqh);
    cudaGetSymbolAddress((void**)&Wkh, g_Wkh);
    cudaGetSymbolAddress((void**)&Wvh, g_Wvh);
    cudaGetSymbolAddress((void**)&Woh, g_Woh);
    cudaGetSymbolAddress((void**)&Ah, g_Ah);
    cudaGetSymbolAddress((void**)&Qah, g_Qah);
    cudaGetSymbolAddress((void**)&Qal, g_Qal);
    cudaGetSymbolAddress((void**)&Kah, g_Kah);
    cudaGetSymbolAddress((void**)&Vt, g_Vt);

    cudaFuncSetAttribute(gemm_fp16x1_atomic, cudaFuncAttributeMaxDynamicSharedMemorySize, GSMEM1_BYTES);
    cudaFuncSetAttribute(gemm_q_rope, cudaFuncAttributeMaxDynamicSharedMemorySize, GQSMEM_BYTES);
    cudaFuncSetAttribute(gemm_k_rope, cudaFuncAttributeMaxDynamicSharedMemorySize, GSMEM_BYTES);
    cudaFuncSetAttribute(gemm_v_t, cudaFuncAttributeMaxDynamicSharedMemorySize, GSMEM1_BYTES);
    cudaFuncSetAttribute(attn_mma, cudaFuncAttributeMaxDynamicSharedMemorySize, ASMEM_BYTES);

    // zero-init only the Wo split-K target
    cudaMemsetAsync(out, 0, (size_t)NT * DIM * sizeof(float));

    // conversions
    split_rows_h<<<(NT * DIM / 4 + 255) / 256, 256>>>(x, xh, xl, NT * DIM / 4);
    transpose_h<<<dim3(QDIM / 64, DIM / 64), 256>>>(Wq, Wqh, DIM, QDIM);
    transpose_h<<<dim3(KDIM / 64, DIM / 64), 256>>>(Wk, Wkh, DIM, KDIM);
    transpose_h<<<dim3(KDIM / 64, DIM / 64), 256>>>(Wv, Wvh, DIM, KDIM);
    transpose_h<<<dim3(DIM / 64, QDIM / 64), 256>>>(Wo, Woh, QDIM, DIM);

    // Q projection (1-term) with fused RoPE + hi/lo split -> Qah/Qal
    gemm_q_rope<<<dim3(QDIM / 256, NT / 128, 1), 256, GQSMEM_BYTES>>>(xh, Wqh, cosT, sinT, Qah, Qal, NT, QDIM, DIM);
    // K projection (2-term) with fused RoPE -> Kah
    gemm_k_rope<<<dim3(KDIM / 256, NT / 128, 1), 256, GSMEM_BYTES>>>(xh, xl, Wkh, cosT, sinT, Kah, NT, KDIM, DIM);
    // V projection (1-term) with fused transpose -> Vt
    gemm_v_t<<<dim3(KDIM / 256, NT / 128, 1), 256, GSMEM1_BYTES>>>(xh, Wvh, Vt, NT, KDIM, DIM);

    // fp16 2-term flash attention -> single fp16 output
    attn_mma<<<1024, 256, ASMEM_BYTES>>>(Qah, Qal, Kah, Vt, Ah);

    // Output projection (fp16 1-term, split-K=2, atomic into zeroed out)
    gemm_fp16x1_atomic<<<dim3(DIM / 256, NT / 128, 2), 256, GSMEM1_BYTES>>>(Ah, Woh, out, NT, DIM, QDIM);
}